// round 1
// baseline (speedup 1.0000x reference)
#include <cuda_runtime.h>
#include <math.h>

#define N_SRC 32768
#define M_TGT 8192
#define D_DIM 64
#define REG_P 0.01f
#define INV_REG 100.0f

#define BM 128
#define BN 128
#define PAD 129          // 64 x 129 k-major tiles, pad kills row-bank aliasing
#define NTHREADS 256

// -------- scratch (no allocs allowed) --------
__device__ float g_tysq[M_TGT];
__device__ float g_c[M_TGT];        // (psi[m] - tysq[m]/mv) / reg
__device__ float g_scalars[4];      // [0]=1/mv  [1]=2/(mv*reg)  [2]=mean(psi)

// -------- kernel A: per-target squared norms --------
__global__ void tysq_kernel(const float* __restrict__ Y) {
    int m = blockIdx.x * blockDim.x + threadIdx.x;
    if (m >= M_TGT) return;
    const float4* row = reinterpret_cast<const float4*>(Y + (size_t)m * D_DIM);
    float acc = 0.f;
#pragma unroll
    for (int i = 0; i < D_DIM / 4; i++) {
        float4 v = row[i];
        acc += v.x * v.x + v.y * v.y + v.z * v.z + v.w * v.w;
    }
    g_tysq[m] = acc;
}

// -------- kernel B: deterministic reductions + c[m] --------
__global__ void prep_kernel(const float* __restrict__ psi) {
    __shared__ float red_t[256];
    __shared__ float red_p[256];
    __shared__ float inv_mv_s;
    int t = threadIdx.x;
    float st = 0.f, sp = 0.f;
    for (int m = t; m < M_TGT; m += 256) { st += g_tysq[m]; sp += psi[m]; }
    red_t[t] = st; red_p[t] = sp;
    __syncthreads();
    for (int off = 128; off > 0; off >>= 1) {
        if (t < off) { red_t[t] += red_t[t + off]; red_p[t] += red_p[t + off]; }
        __syncthreads();
    }
    if (t == 0) {
        float mv = red_t[0] / (float)M_TGT;
        float inv_mv = 1.0f / mv;
        g_scalars[0] = inv_mv;
        g_scalars[1] = 2.0f * inv_mv * INV_REG;
        g_scalars[2] = red_p[0] / (float)M_TGT;
        inv_mv_s = inv_mv;
    }
    __syncthreads();
    float inv_mv = inv_mv_s;
    for (int m = t; m < M_TGT; m += 256)
        g_c[m] = (psi[m] - g_tysq[m] * inv_mv) * INV_REG;
}

// -------- main kernel: tiled dot + online logsumexp --------
extern __shared__ float smem[];

__global__ __launch_bounds__(NTHREADS)
void lse_kernel(const float* __restrict__ X, const float* __restrict__ Y,
                float* __restrict__ out) {
    float* Xs = smem;                       // [64][PAD]  (k-major)
    float* Ys = smem + D_DIM * PAD;         // [64][PAD]
    float* cs = smem + 2 * D_DIM * PAD;     // [BN]

    const int t  = threadIdx.x;
    const int tx = t & 15;                  // 0..15 -> 8 target cols each
    const int ty = t >> 4;                  // 0..15 -> 8 source rows each
    const int rowBase = blockIdx.x * BM;

    // ---- load X tile (once), k-major with pad ----
    {
        const int r0 = ty;                  // row 0..15, +i*16
        const int kc = tx;                  // float4 chunk 0..15
#pragma unroll
        for (int i = 0; i < 8; i++) {
            int r = r0 + i * 16;
            float4 v = *reinterpret_cast<const float4*>(
                X + (size_t)(rowBase + r) * D_DIM + kc * 4);
            Xs[(kc * 4 + 0) * PAD + r] = v.x;
            Xs[(kc * 4 + 1) * PAD + r] = v.y;
            Xs[(kc * 4 + 2) * PAD + r] = v.z;
            Xs[(kc * 4 + 3) * PAD + r] = v.w;
        }
    }
    __syncthreads();

    // ---- x_sq for the 8 rows this (tx==0) lane will write ----
    float xsq[8];
    if (tx == 0) {
#pragma unroll
        for (int i = 0; i < 8; i++) {
            int r = ty * 8 + i;
            float a = 0.f;
            for (int k = 0; k < D_DIM; k++) {
                float v = Xs[k * PAD + r];
                a = fmaf(v, v, a);
            }
            xsq[i] = a;
        }
    }

    const float sscale  = g_scalars[1];

    float runm[8], runs[8];
#pragma unroll
    for (int i = 0; i < 8; i++) { runm[i] = -INFINITY; runs[i] = 0.f; }

    for (int mt = 0; mt < M_TGT; mt += BN) {
        __syncthreads();   // previous iteration done with Ys/cs
        {
            const int r0 = ty, kc = tx;
#pragma unroll
            for (int i = 0; i < 8; i++) {
                int r = r0 + i * 16;
                float4 v = *reinterpret_cast<const float4*>(
                    Y + (size_t)(mt + r) * D_DIM + kc * 4);
                Ys[(kc * 4 + 0) * PAD + r] = v.x;
                Ys[(kc * 4 + 1) * PAD + r] = v.y;
                Ys[(kc * 4 + 2) * PAD + r] = v.z;
                Ys[(kc * 4 + 3) * PAD + r] = v.w;
            }
        }
        if (t < BN) cs[t] = g_c[mt + t];
        __syncthreads();

        float acc[8][8];
#pragma unroll
        for (int i = 0; i < 8; i++)
#pragma unroll
            for (int j = 0; j < 8; j++) acc[i][j] = 0.f;

#pragma unroll 4
        for (int k = 0; k < D_DIM; k++) {
            float xr[8], yr[8];
#pragma unroll
            for (int i = 0; i < 8; i++) xr[i] = Xs[k * PAD + ty * 8 + i];
#pragma unroll
            for (int j = 0; j < 8; j++) yr[j] = Ys[k * PAD + tx * 8 + j];
#pragma unroll
            for (int i = 0; i < 8; i++)
#pragma unroll
                for (int j = 0; j < 8; j++)
                    acc[i][j] = fmaf(xr[i], yr[j], acc[i][j]);
        }

        // epilogue: arg = c[m] + s * dot ; online (max, sum)
#pragma unroll
        for (int i = 0; i < 8; i++) {
            float tmax = -INFINITY;
#pragma unroll
            for (int j = 0; j < 8; j++) {
                acc[i][j] = fmaf(sscale, acc[i][j], cs[tx * 8 + j]);
                tmax = fmaxf(tmax, acc[i][j]);
            }
            if (tmax > runm[i]) {
                runs[i] *= __expf(runm[i] - tmax);
                runm[i] = tmax;
            }
            float se = 0.f;
#pragma unroll
            for (int j = 0; j < 8; j++) se += __expf(acc[i][j] - runm[i]);
            runs[i] += se;
        }
    }

    // ---- merge (m,s) across the 16 lanes sharing each row ----
    const float inv_mv   = g_scalars[0];
    const float mean_psi = g_scalars[2];
#pragma unroll
    for (int i = 0; i < 8; i++) {
        float m  = runm[i];
        float sv = runs[i];
#pragma unroll
        for (int off = 8; off > 0; off >>= 1) {
            float m2 = __shfl_down_sync(0xffffffffu, m,  off, 16);
            float s2 = __shfl_down_sync(0xffffffffu, sv, off, 16);
            float nm = fmaxf(m, m2);
            sv = sv * __expf(m - nm) + s2 * __expf(m2 - nm);
            m = nm;
        }
        if (tx == 0) {
            int row = rowBase + ty * 8 + i;
            // out = xsq/mv - reg*(m + log s) + mean(psi)
            out[row] = fmaf(xsq[i], inv_mv, -REG_P * (m + __logf(sv)) + mean_psi);
        }
    }
}

// -------- launch --------
extern "C" void kernel_launch(void* const* d_in, const int* in_sizes, int n_in,
                              void* d_out, int out_size) {
    const float *X = nullptr, *Y = nullptr, *psi = nullptr;
    for (int i = 0; i < n_in; i++) {
        if (in_sizes[i] == N_SRC * D_DIM)      X   = (const float*)d_in[i];
        else if (in_sizes[i] == M_TGT * D_DIM) Y   = (const float*)d_in[i];
        else if (in_sizes[i] == M_TGT)         psi = (const float*)d_in[i];
    }
    float* out = (float*)d_out;

    tysq_kernel<<<(M_TGT + 255) / 256, 256>>>(Y);
    prep_kernel<<<1, 256>>>(psi);

    size_t smem_bytes = (size_t)(2 * D_DIM * PAD + BN) * sizeof(float);
    cudaFuncSetAttribute(lse_kernel,
                         cudaFuncAttributeMaxDynamicSharedMemorySize,
                         (int)smem_bytes);
    lse_kernel<<<N_SRC / BM, NTHREADS, smem_bytes>>>(X, Y, out);
}

// round 4
// speedup vs baseline: 3.1221x; 3.1221x over previous
#include <cuda_runtime.h>
#include <math.h>
#include <cstdint>

#define N_SRC 32768
#define M_TGT 8192
#define D_DIM 64
#define REG_P 0.01f
#define INV_REG 100.0f
#define LOG2E 1.4426950408889634f
#define LN2 0.6931471805599453f

#define BM 128
#define BN 128
#define NT 256
#define NTILES (M_TGT / BN)   // 64

// ---------------- scratch ----------------
__device__ float g_tysq[M_TGT];
__device__ float g_c2[M_TGT];       // (psi - tysq/mv) * INV_REG * LOG2E
__device__ float g_scalars[4];      // 0: 1/mv, 1: 2*invmv*INV_REG*LOG2E, 2: mean(psi)

// ---------------- helpers ----------------
__device__ __forceinline__ uint32_t smem_u32(const void* p) {
    uint32_t a;
    asm("{ .reg .u64 t; cvta.to.shared.u64 t, %1; cvt.u32.u64 %0, t; }" : "=r"(a) : "l"(p));
    return a;
}
__device__ __forceinline__ uint64_t gmem_u64(const void* p) {
    uint64_t a;
    asm("cvta.to.global.u64 %0, %1;" : "=l"(a) : "l"(p));
    return a;
}
__device__ __forceinline__ float ex2f(float x) {
    float r; asm("ex2.approx.ftz.f32 %0, %1;" : "=f"(r) : "f"(x)); return r;
}
__device__ __forceinline__ float lg2f(float x) {
    float r; asm("lg2.approx.f32 %0, %1;" : "=f"(r) : "f"(x)); return r;
}

#define CP_ASYNC16(s, g) \
    asm volatile("cp.async.cg.shared.global [%0], [%1], 16;" :: "r"(s), "l"(g))
#define CP_COMMIT() asm volatile("cp.async.commit_group;" ::: "memory")
#define CP_WAIT(n)  asm volatile("cp.async.wait_group %0;" :: "n"(n) : "memory")

__device__ __forceinline__ void ldsm4(uint32_t* r, uint32_t addr) {
    asm volatile("ldmatrix.sync.aligned.m8n8.x4.shared.b16 {%0,%1,%2,%3}, [%4];"
                 : "=r"(r[0]), "=r"(r[1]), "=r"(r[2]), "=r"(r[3]) : "r"(addr));
}
__device__ __forceinline__ void mma_tf32(float* c, const uint32_t* a,
                                         uint32_t b0, uint32_t b1) {
    asm volatile("mma.sync.aligned.m16n8k8.row.col.f32.tf32.tf32.f32 "
                 "{%0,%1,%2,%3}, {%4,%5,%6,%7}, {%8,%9}, {%0,%1,%2,%3};"
                 : "+f"(c[0]), "+f"(c[1]), "+f"(c[2]), "+f"(c[3])
                 : "r"(a[0]), "r"(a[1]), "r"(a[2]), "r"(a[3]), "r"(b0), "r"(b1));
}

// smem layout (bytes): Xs 32KB | Ys 2x32KB | cs 2x512B
#define SM_X 0
#define SM_Y 32768
#define SM_C (32768 + 65536)
#define SM_TOTAL (SM_C + 1024)

// ---------------- kernel A: per-target squared norms ----------------
__global__ void tysq_kernel(const float* __restrict__ Y) {
    int m = blockIdx.x * blockDim.x + threadIdx.x;
    if (m >= M_TGT) return;
    const float4* row = reinterpret_cast<const float4*>(Y + (size_t)m * D_DIM);
    float acc = 0.f;
#pragma unroll
    for (int i = 0; i < D_DIM / 4; i++) {
        float4 v = row[i];
        acc += v.x * v.x + v.y * v.y + v.z * v.z + v.w * v.w;
    }
    g_tysq[m] = acc;
}

// ---------------- kernel B: deterministic reductions + c2[m] ----------------
__global__ void prep_kernel(const float* __restrict__ psi) {
    __shared__ float red_t[256];
    __shared__ float red_p[256];
    __shared__ float inv_mv_s;
    int t = threadIdx.x;
    float st = 0.f, sp = 0.f;
    for (int m = t; m < M_TGT; m += 256) { st += g_tysq[m]; sp += psi[m]; }
    red_t[t] = st; red_p[t] = sp;
    __syncthreads();
    for (int off = 128; off > 0; off >>= 1) {
        if (t < off) { red_t[t] += red_t[t + off]; red_p[t] += red_p[t + off]; }
        __syncthreads();
    }
    if (t == 0) {
        float mv = red_t[0] / (float)M_TGT;
        float inv_mv = 1.0f / mv;
        g_scalars[0] = inv_mv;
        g_scalars[1] = 2.0f * inv_mv * INV_REG * LOG2E;
        g_scalars[2] = red_p[0] / (float)M_TGT;
        inv_mv_s = inv_mv;
    }
    __syncthreads();
    float inv_mv = inv_mv_s;
    for (int m = t; m < M_TGT; m += 256)
        g_c2[m] = (psi[m] - g_tysq[m] * inv_mv) * (INV_REG * LOG2E);
}

// ---------------- main kernel ----------------
extern __shared__ char smem[];

__global__ __launch_bounds__(NT, 1)
void lse_mma_kernel(const float* __restrict__ X, const float* __restrict__ Y,
                    float* __restrict__ out) {
    const uint32_t sb = smem_u32(smem);
    const int tid  = threadIdx.x;
    const int lane = tid & 31;
    const int wid  = tid >> 5;
    const int mwarp = wid >> 1;          // 0..3 -> rows mwarp*32..+31
    const int nwarp = wid & 1;           // 0..1 -> cols nwarp*64..+63
    const int q  = lane & 3;
    const int g4 = lane >> 2;
    const int rowBase = blockIdx.x * BM;

    const float invmv = g_scalars[0];
    const float s2    = g_scalars[1];
    const float mpsi  = g_scalars[2];

    const uint64_t Yg = gmem_u64(Y);
    const uint64_t Cg = gmem_u64(g_c2);

    // ---- prefetch Y tiles 0,1 (cp.async, swizzled) ----
#pragma unroll
    for (int pt = 0; pt < 2; pt++) {
#pragma unroll
        for (int i = 0; i < 8; i++) {
            int idx = tid + i * NT;
            int row = idx >> 4, ch = idx & 15;
            uint32_t s = sb + SM_Y + pt * 32768 + row * 256 + ((ch ^ (row & 7)) << 4);
            uint64_t g = Yg + (uint64_t)((pt * BN + row) * D_DIM + ch * 4) * 4;
            CP_ASYNC16(s, g);
        }
        if (tid < 32) {
            uint32_t s = sb + SM_C + pt * 512 + tid * 16;
            uint64_t g = Cg + (uint64_t)(pt * BN + tid * 4) * 4;
            CP_ASYNC16(s, g);
        }
        CP_COMMIT();
    }

    // ---- X tile -> smem (swizzled) ----
#pragma unroll
    for (int i = 0; i < 8; i++) {
        int idx = tid + i * NT;
        int row = idx >> 4, ch = idx & 15;
        float4 v = *reinterpret_cast<const float4*>(
            X + (size_t)(rowBase + row) * D_DIM + ch * 4);
        *reinterpret_cast<float4*>(smem + SM_X + row * 256 + ((ch ^ (row & 7)) << 4)) = v;
    }
    __syncthreads();

    // ---- A fragments (register-resident, rounded to tf32) ----
    uint32_t A[2][8][4];
    {
        const int b = lane >> 3, lr = lane & 7;
        const int rsel = (b & 1) * 8, csel = b >> 1;
#pragma unroll
        for (int mt = 0; mt < 2; mt++)
#pragma unroll
            for (int ks = 0; ks < 8; ks++) {
                int row = mwarp * 32 + mt * 16 + rsel + lr;
                int ch  = ks * 2 + csel;
                uint32_t ad = sb + SM_X + row * 256 + ((ch ^ lr) << 4);
                ldsm4(A[mt][ks], ad);
            }
#pragma unroll
        for (int mt = 0; mt < 2; mt++)
#pragma unroll
            for (int ks = 0; ks < 8; ks++)
#pragma unroll
                for (int j = 0; j < 4; j++) {
                    float f = __uint_as_float(A[mt][ks][j]);
                    uint32_t o;
                    asm("cvt.rna.tf32.f32 %0, %1;" : "=r"(o) : "f"(f));
                    A[mt][ks][j] = o;
                }
    }

    const int bB = lane >> 3, lrB = lane & 7;
    const int rselB = (bB >> 1) * 8, cselB = bB & 1;

    float runm[4], runs[4];
#pragma unroll
    for (int r = 0; r < 4; r++) { runm[r] = -INFINITY; runs[r] = 0.f; }

    for (int t = 0; t < NTILES; t++) {
        if (t < NTILES - 1) { CP_WAIT(1); } else { CP_WAIT(0); }
        __syncthreads();
        const int buf = t & 1;
        const uint32_t yb = sb + SM_Y + buf * 32768;

        float acc[2][8][4];
#pragma unroll
        for (int mt = 0; mt < 2; mt++)
#pragma unroll
            for (int nt = 0; nt < 8; nt++)
#pragma unroll
                for (int j = 0; j < 4; j++) acc[mt][nt][j] = 0.f;

#pragma unroll
        for (int nt2 = 0; nt2 < 4; nt2++) {
            const uint32_t rowb =
                yb + (uint32_t)(nwarp * 64 + nt2 * 16 + rselB + lrB) * 256;
#pragma unroll
            for (int ks = 0; ks < 8; ks++) {
                uint32_t B[4];
                uint32_t ad = rowb + (((ks * 2 + cselB) ^ lrB) << 4);
                ldsm4(B, ad);
#pragma unroll
                for (int mt = 0; mt < 2; mt++) {
                    mma_tf32(acc[mt][nt2 * 2 + 0], A[mt][ks], B[0], B[1]);
                    mma_tf32(acc[mt][nt2 * 2 + 1], A[mt][ks], B[2], B[3]);
                }
            }
        }

        // ---- fused epilogue: v = c + s2*dot (log2 domain), online lse ----
        float2 cpv[8];
        {
            const float* cbB = reinterpret_cast<const float*>(smem + SM_C + buf * 512)
                               + nwarp * 64;
#pragma unroll
            for (int nt = 0; nt < 8; nt++)
                cpv[nt] = *reinterpret_cast<const float2*>(cbB + nt * 8 + q * 2);
        }
#pragma unroll
        for (int mt = 0; mt < 2; mt++) {
            float vA[16], vB[16];
            float mA = -INFINITY, mB = -INFINITY;
#pragma unroll
            for (int nt = 0; nt < 8; nt++) {
                float a0 = fmaf(s2, acc[mt][nt][0], cpv[nt].x);
                float a1 = fmaf(s2, acc[mt][nt][1], cpv[nt].y);
                float b0 = fmaf(s2, acc[mt][nt][2], cpv[nt].x);
                float b1 = fmaf(s2, acc[mt][nt][3], cpv[nt].y);
                vA[nt * 2] = a0; vA[nt * 2 + 1] = a1;
                vB[nt * 2] = b0; vB[nt * 2 + 1] = b1;
                mA = fmaxf(mA, fmaxf(a0, a1));
                mB = fmaxf(mB, fmaxf(b0, b1));
            }
            const int r0 = mt * 2, r1 = mt * 2 + 1;
            if (mA > runm[r0] - 25.f) {
                if (mA > runm[r0]) { runs[r0] *= ex2f(runm[r0] - mA); runm[r0] = mA; }
                float s0 = 0.f, s1 = 0.f;
#pragma unroll
                for (int j = 0; j < 16; j += 2) {
                    s0 += ex2f(vA[j]     - runm[r0]);
                    s1 += ex2f(vA[j + 1] - runm[r0]);
                }
                runs[r0] += s0 + s1;
            }
            if (mB > runm[r1] - 25.f) {
                if (mB > runm[r1]) { runs[r1] *= ex2f(runm[r1] - mB); runm[r1] = mB; }
                float s0 = 0.f, s1 = 0.f;
#pragma unroll
                for (int j = 0; j < 16; j += 2) {
                    s0 += ex2f(vB[j]     - runm[r1]);
                    s1 += ex2f(vB[j + 1] - runm[r1]);
                }
                runs[r1] += s0 + s1;
            }
        }

        __syncthreads();   // everyone done with Ys[buf]/cs[buf]
        if (t + 2 < NTILES) {
            const int nt2i = t + 2;
#pragma unroll
            for (int i = 0; i < 8; i++) {
                int idx = tid + i * NT;
                int row = idx >> 4, ch = idx & 15;
                uint32_t s = sb + SM_Y + buf * 32768 + row * 256 + ((ch ^ (row & 7)) << 4);
                uint64_t g = Yg + (uint64_t)((nt2i * BN + row) * D_DIM + ch * 4) * 4;
                CP_ASYNC16(s, g);
            }
            if (tid < 32) {
                uint32_t s = sb + SM_C + buf * 512 + tid * 16;
                uint64_t g = Cg + (uint64_t)(nt2i * BN + tid * 4) * 4;
                CP_ASYNC16(s, g);
            }
            CP_COMMIT();
        }
    }

    // ---- reduce across the 4 lanes sharing each row ----
    float fm[4], fs[4];
#pragma unroll
    for (int r = 0; r < 4; r++) {
        float m = runm[r], s = runs[r];
#pragma unroll
        for (int off = 1; off < 4; off <<= 1) {
            float m2 = __shfl_xor_sync(0xffffffffu, m, off);
            float s2x = __shfl_xor_sync(0xffffffffu, s, off);
            float nm = fmaxf(m, m2);
            s = s * ex2f(m - nm) + s2x * ex2f(m2 - nm);
            m = nm;
        }
        fm[r] = m; fs[r] = s;
    }

    __syncthreads();                    // Xs smem reusable
    float* pm = reinterpret_cast<float*>(smem);   // [2][128]
    float* ps = pm + 256;
    if (q == 0) {
#pragma unroll
        for (int r = 0; r < 4; r++) {
            int mt = r >> 1, hf = r & 1;
            int rl = mwarp * 32 + mt * 16 + hf * 8 + g4;
            pm[nwarp * 128 + rl] = fm[r];
            ps[nwarp * 128 + rl] = fs[r];
        }
    }
    __syncthreads();
    if (tid < BM) {
        float ma = pm[tid], mb = pm[128 + tid];
        float sa = ps[tid], sb2 = ps[128 + tid];
        float mM = fmaxf(ma, mb);
        float ss = sa * ex2f(ma - mM) + sb2 * ex2f(mb - mM);
        const float4* xr = reinterpret_cast<const float4*>(
            X + (size_t)(rowBase + tid) * D_DIM);
        float xs = 0.f;
#pragma unroll
        for (int i = 0; i < 16; i++) {
            float4 v = xr[i];
            xs = fmaf(v.x, v.x, fmaf(v.y, v.y, fmaf(v.z, v.z, fmaf(v.w, v.w, xs))));
        }
        out[rowBase + tid] = fmaf(xs, invmv, mpsi) - (REG_P * LN2) * (mM + lg2f(ss));
    }
}

// ---------------- launch ----------------
extern "C" void kernel_launch(void* const* d_in, const int* in_sizes, int n_in,
                              void* d_out, int out_size) {
    const float *X = nullptr, *Y = nullptr, *psi = nullptr;
    for (int i = 0; i < n_in; i++) {
        if (in_sizes[i] == N_SRC * D_DIM)      X   = (const float*)d_in[i];
        else if (in_sizes[i] == M_TGT * D_DIM) Y   = (const float*)d_in[i];
        else if (in_sizes[i] == M_TGT)         psi = (const float*)d_in[i];
    }
    float* out = (float*)d_out;

    tysq_kernel<<<(M_TGT + 255) / 256, 256>>>(Y);
    prep_kernel<<<1, 256>>>(psi);

    cudaFuncSetAttribute(lse_mma_kernel,
                         cudaFuncAttributeMaxDynamicSharedMemorySize, SM_TOTAL);
    lse_mma_kernel<<<N_SRC / BM, NT, SM_TOTAL>>>(X, Y, out);
}

// round 5
// speedup vs baseline: 3.3034x; 1.0581x over previous
#include <cuda_runtime.h>
#include <math.h>
#include <cstdint>

#define N_SRC 32768
#define M_TGT 8192
#define D_DIM 64
#define REG_P 0.01f
#define INV_REG 100.0f
#define LOG2E 1.4426950408889634f
#define LN2 0.6931471805599453f

#define BM 128
#define BN 128
#define NT 256
#define NTILES (M_TGT / BN)   // 64
#define NSTAGE 4

// ---------------- scratch ----------------
__device__ float g_tysq[M_TGT];
__device__ float g_c2[M_TGT];       // (psi - tysq/mv) * INV_REG * LOG2E
__device__ float g_scalars[4];      // 0: 1/mv, 1: 2*invmv*INV_REG*LOG2E, 2: mean(psi)

// ---------------- helpers ----------------
__device__ __forceinline__ uint32_t smem_u32(const void* p) {
    uint32_t a;
    asm("{ .reg .u64 t; cvta.to.shared.u64 t, %1; cvt.u32.u64 %0, t; }" : "=r"(a) : "l"(p));
    return a;
}
__device__ __forceinline__ uint64_t gmem_u64(const void* p) {
    uint64_t a;
    asm("cvta.to.global.u64 %0, %1;" : "=l"(a) : "l"(p));
    return a;
}
__device__ __forceinline__ float ex2f(float x) {
    float r; asm("ex2.approx.ftz.f32 %0, %1;" : "=f"(r) : "f"(x)); return r;
}
__device__ __forceinline__ float lg2f(float x) {
    float r; asm("lg2.approx.f32 %0, %1;" : "=f"(r) : "f"(x)); return r;
}

#define CP_ASYNC16(s, g) \
    asm volatile("cp.async.cg.shared.global [%0], [%1], 16;" :: "r"(s), "l"(g))
#define CP_COMMIT() asm volatile("cp.async.commit_group;" ::: "memory")
#define CP_WAIT(n)  asm volatile("cp.async.wait_group %0;" :: "n"(n) : "memory")

__device__ __forceinline__ void ldsm4(uint32_t* r, uint32_t addr) {
    asm volatile("ldmatrix.sync.aligned.m8n8.x4.shared.b16 {%0,%1,%2,%3}, [%4];"
                 : "=r"(r[0]), "=r"(r[1]), "=r"(r[2]), "=r"(r[3]) : "r"(addr));
}
__device__ __forceinline__ void mma_tf32(float* c, const uint32_t* a,
                                         uint32_t b0, uint32_t b1) {
    asm volatile("mma.sync.aligned.m16n8k8.row.col.f32.tf32.tf32.f32 "
                 "{%0,%1,%2,%3}, {%4,%5,%6,%7}, {%8,%9}, {%0,%1,%2,%3};"
                 : "+f"(c[0]), "+f"(c[1]), "+f"(c[2]), "+f"(c[3])
                 : "r"(a[0]), "r"(a[1]), "r"(a[2]), "r"(a[3]), "r"(b0), "r"(b1));
}

// smem layout (bytes): Xs 32KB | Ys 4x32KB | cs 4x512B
#define SM_X 0
#define SM_Y 32768
#define SM_C (32768 + 131072)
#define SM_TOTAL (SM_C + 2048)      // 165,888

// ---------------- kernel A: per-target squared norms ----------------
__global__ void tysq_kernel(const float* __restrict__ Y) {
    int m = blockIdx.x * blockDim.x + threadIdx.x;
    if (m >= M_TGT) return;
    const float4* row = reinterpret_cast<const float4*>(Y + (size_t)m * D_DIM);
    float acc = 0.f;
#pragma unroll
    for (int i = 0; i < D_DIM / 4; i++) {
        float4 v = row[i];
        acc += v.x * v.x + v.y * v.y + v.z * v.z + v.w * v.w;
    }
    g_tysq[m] = acc;
}

// ---------------- kernel B: deterministic reductions + c2[m] ----------------
__global__ void prep_kernel(const float* __restrict__ psi) {
    __shared__ float red_t[256];
    __shared__ float red_p[256];
    __shared__ float inv_mv_s;
    int t = threadIdx.x;
    float st = 0.f, sp = 0.f;
    for (int m = t; m < M_TGT; m += 256) { st += g_tysq[m]; sp += psi[m]; }
    red_t[t] = st; red_p[t] = sp;
    __syncthreads();
    for (int off = 128; off > 0; off >>= 1) {
        if (t < off) { red_t[t] += red_t[t + off]; red_p[t] += red_p[t + off]; }
        __syncthreads();
    }
    if (t == 0) {
        float mv = red_t[0] / (float)M_TGT;
        float inv_mv = 1.0f / mv;
        g_scalars[0] = inv_mv;
        g_scalars[1] = 2.0f * inv_mv * INV_REG * LOG2E;
        g_scalars[2] = red_p[0] / (float)M_TGT;
        inv_mv_s = inv_mv;
    }
    __syncthreads();
    float inv_mv = inv_mv_s;
    for (int m = t; m < M_TGT; m += 256)
        g_c2[m] = (psi[m] - g_tysq[m] * inv_mv) * (INV_REG * LOG2E);
}

// ---------------- main kernel ----------------
extern __shared__ char smem[];

__global__ __launch_bounds__(NT, 1)
void lse_mma_kernel(const float* __restrict__ X, const float* __restrict__ Y,
                    float* __restrict__ out) {
    const uint32_t sb = smem_u32(smem);
    const int tid  = threadIdx.x;
    const int lane = tid & 31;
    const int wid  = tid >> 5;
    const int mwarp = wid >> 1;          // 0..3 -> rows mwarp*32..+31
    const int nwarp = wid & 1;           // 0..1 -> cols nwarp*64..+63
    const int q  = lane & 3;
    const int g4 = lane >> 2;
    const int rowBase = blockIdx.x * BM;

    const float invmv = g_scalars[0];
    const float s2    = g_scalars[1];
    const float mpsi  = g_scalars[2];

    const uint64_t Yg = gmem_u64(Y);
    const uint64_t Cg = gmem_u64(g_c2);

    // ---- prefetch Y tiles 0..2 (3 stages in flight) ----
#pragma unroll
    for (int pt = 0; pt < NSTAGE - 1; pt++) {
#pragma unroll
        for (int i = 0; i < 8; i++) {
            int idx = tid + i * NT;
            int row = idx >> 4, ch = idx & 15;
            uint32_t s = sb + SM_Y + pt * 32768 + row * 256 + ((ch ^ (row & 7)) << 4);
            uint64_t g = Yg + (uint64_t)((pt * BN + row) * D_DIM + ch * 4) * 4;
            CP_ASYNC16(s, g);
        }
        if (tid < 32) {
            uint32_t s = sb + SM_C + pt * 512 + tid * 16;
            uint64_t g = Cg + (uint64_t)(pt * BN + tid * 4) * 4;
            CP_ASYNC16(s, g);
        }
        CP_COMMIT();
    }

    // ---- X tile -> smem (swizzled) ----
#pragma unroll
    for (int i = 0; i < 8; i++) {
        int idx = tid + i * NT;
        int row = idx >> 4, ch = idx & 15;
        float4 v = *reinterpret_cast<const float4*>(
            X + (size_t)(rowBase + row) * D_DIM + ch * 4);
        *reinterpret_cast<float4*>(smem + SM_X + row * 256 + ((ch ^ (row & 7)) << 4)) = v;
    }
    __syncthreads();

    // ---- A fragments (register-resident, rounded to tf32) ----
    uint32_t A[2][8][4];
    {
        const int b = lane >> 3, lr = lane & 7;
        const int rsel = (b & 1) * 8, csel = b >> 1;
#pragma unroll
        for (int mt = 0; mt < 2; mt++)
#pragma unroll
            for (int ks = 0; ks < 8; ks++) {
                int row = mwarp * 32 + mt * 16 + rsel + lr;
                int ch  = ks * 2 + csel;
                uint32_t ad = sb + SM_X + row * 256 + ((ch ^ lr) << 4);
                ldsm4(A[mt][ks], ad);
            }
#pragma unroll
        for (int mt = 0; mt < 2; mt++)
#pragma unroll
            for (int ks = 0; ks < 8; ks++)
#pragma unroll
                for (int j = 0; j < 4; j++) {
                    float f = __uint_as_float(A[mt][ks][j]);
                    uint32_t o;
                    asm("cvt.rna.tf32.f32 %0, %1;" : "=r"(o) : "f"(f));
                    A[mt][ks][j] = o;
                }
    }

    const int bB = lane >> 3, lrB = lane & 7;
    const int rselB = (bB >> 1) * 8, cselB = bB & 1;

    float runm[4], runs[4];
#pragma unroll
    for (int r = 0; r < 4; r++) { runm[r] = -INFINITY; runs[r] = 0.f; }

    for (int t = 0; t < NTILES; t++) {
        CP_WAIT(2);                      // stage t complete (3 groups always live)
        __syncthreads();                 // all warps: t visible, stage (t-1)&3 free
        const int buf = t & (NSTAGE - 1);
        const uint32_t yb = sb + SM_Y + buf * 32768;

        // issue cp for tile t+3 into stage (t+3)&3 (== (t-1)&3); empty group otherwise
        if (t + NSTAGE - 1 < NTILES) {
            const int ft = t + NSTAGE - 1;
            const int fb = ft & (NSTAGE - 1);
#pragma unroll
            for (int i = 0; i < 8; i++) {
                int idx = tid + i * NT;
                int row = idx >> 4, ch = idx & 15;
                uint32_t s = sb + SM_Y + fb * 32768 + row * 256 + ((ch ^ (row & 7)) << 4);
                uint64_t g = Yg + (uint64_t)((ft * BN + row) * D_DIM + ch * 4) * 4;
                CP_ASYNC16(s, g);
            }
            if (tid < 32) {
                uint32_t s = sb + SM_C + fb * 512 + tid * 16;
                uint64_t g = Cg + (uint64_t)(ft * BN + tid * 4) * 4;
                CP_ASYNC16(s, g);
            }
        }
        CP_COMMIT();                     // always commit (possibly empty group)

        // c fragments early (independent of MMA; hides LDS latency)
        float2 cpv[8];
        {
            const float* cbB = reinterpret_cast<const float*>(smem + SM_C + buf * 512)
                               + nwarp * 64;
#pragma unroll
            for (int nt = 0; nt < 8; nt++)
                cpv[nt] = *reinterpret_cast<const float2*>(cbB + nt * 8 + q * 2);
        }

        float acc[2][8][4];
#pragma unroll
        for (int mt = 0; mt < 2; mt++)
#pragma unroll
            for (int nt = 0; nt < 8; nt++)
#pragma unroll
                for (int j = 0; j < 4; j++) acc[mt][nt][j] = 0.f;

#pragma unroll
        for (int nt2 = 0; nt2 < 4; nt2++) {
            const uint32_t rowb =
                yb + (uint32_t)(nwarp * 64 + nt2 * 16 + rselB + lrB) * 256;
#pragma unroll
            for (int ks = 0; ks < 8; ks++) {
                uint32_t B[4];
                uint32_t ad = rowb + (((ks * 2 + cselB) ^ lrB) << 4);
                ldsm4(B, ad);
#pragma unroll
                for (int mt = 0; mt < 2; mt++) {
                    mma_tf32(acc[mt][nt2 * 2 + 0], A[mt][ks], B[0], B[1]);
                    mma_tf32(acc[mt][nt2 * 2 + 1], A[mt][ks], B[2], B[3]);
                }
            }
        }

        // ---- fused epilogue: v = c + s2*dot (log2 domain), online lse ----
#pragma unroll
        for (int mt = 0; mt < 2; mt++) {
            float vA[16], vB[16];
            float mA = -INFINITY, mB = -INFINITY;
#pragma unroll
            for (int nt = 0; nt < 8; nt++) {
                float a0 = fmaf(s2, acc[mt][nt][0], cpv[nt].x);
                float a1 = fmaf(s2, acc[mt][nt][1], cpv[nt].y);
                float b0 = fmaf(s2, acc[mt][nt][2], cpv[nt].x);
                float b1 = fmaf(s2, acc[mt][nt][3], cpv[nt].y);
                vA[nt * 2] = a0; vA[nt * 2 + 1] = a1;
                vB[nt * 2] = b0; vB[nt * 2 + 1] = b1;
                mA = fmaxf(mA, fmaxf(a0, a1));
                mB = fmaxf(mB, fmaxf(b0, b1));
            }
            const int r0 = mt * 2, r1 = mt * 2 + 1;
            if (mA > runm[r0] - 20.f) {
                if (mA > runm[r0]) { runs[r0] *= ex2f(runm[r0] - mA); runm[r0] = mA; }
                float s0 = 0.f, s1 = 0.f;
#pragma unroll
                for (int j = 0; j < 16; j += 2) {
                    s0 += ex2f(vA[j]     - runm[r0]);
                    s1 += ex2f(vA[j + 1] - runm[r0]);
                }
                runs[r0] += s0 + s1;
            }
            if (mB > runm[r1] - 20.f) {
                if (mB > runm[r1]) { runs[r1] *= ex2f(runm[r1] - mB); runm[r1] = mB; }
                float s0 = 0.f, s1 = 0.f;
#pragma unroll
                for (int j = 0; j < 16; j += 2) {
                    s0 += ex2f(vB[j]     - runm[r1]);
                    s1 += ex2f(vB[j + 1] - runm[r1]);
                }
                runs[r1] += s0 + s1;
            }
        }
        // no second barrier: stage protection handled by the single sync at loop top
    }

    // ---- reduce across the 4 lanes sharing each row ----
    float fm[4], fs[4];
#pragma unroll
    for (int r = 0; r < 4; r++) {
        float m = runm[r], s = runs[r];
#pragma unroll
        for (int off = 1; off < 4; off <<= 1) {
            float m2 = __shfl_xor_sync(0xffffffffu, m, off);
            float s2x = __shfl_xor_sync(0xffffffffu, s, off);
            float nm = fmaxf(m, m2);
            s = s * ex2f(m - nm) + s2x * ex2f(m2 - nm);
            m = nm;
        }
        fm[r] = m; fs[r] = s;
    }

    __syncthreads();                    // Xs smem reusable
    float* pm = reinterpret_cast<float*>(smem);   // [2][128]
    float* ps = pm + 256;
    if (q == 0) {
#pragma unroll
        for (int r = 0; r < 4; r++) {
            int mt = r >> 1, hf = r & 1;
            int rl = mwarp * 32 + mt * 16 + hf * 8 + g4;
            pm[nwarp * 128 + rl] = fm[r];
            ps[nwarp * 128 + rl] = fs[r];
        }
    }
    __syncthreads();
    if (tid < BM) {
        float ma = pm[tid], mb = pm[128 + tid];
        float sa = ps[tid], sb2 = ps[128 + tid];
        float mM = fmaxf(ma, mb);
        float ss = sa * ex2f(ma - mM) + sb2 * ex2f(mb - mM);
        const float4* xr = reinterpret_cast<const float4*>(
            X + (size_t)(rowBase + tid) * D_DIM);
        float xs = 0.f;
#pragma unroll
        for (int i = 0; i < 16; i++) {
            float4 v = xr[i];
            xs = fmaf(v.x, v.x, fmaf(v.y, v.y, fmaf(v.z, v.z, fmaf(v.w, v.w, xs))));
        }
        out[rowBase + tid] = fmaf(xs, invmv, mpsi) - (REG_P * LN2) * (mM + lg2f(ss));
    }
}

// ---------------- launch ----------------
extern "C" void kernel_launch(void* const* d_in, const int* in_sizes, int n_in,
                              void* d_out, int out_size) {
    const float *X = nullptr, *Y = nullptr, *psi = nullptr;
    for (int i = 0; i < n_in; i++) {
        if (in_sizes[i] == N_SRC * D_DIM)      X   = (const float*)d_in[i];
        else if (in_sizes[i] == M_TGT * D_DIM) Y   = (const float*)d_in[i];
        else if (in_sizes[i] == M_TGT)         psi = (const float*)d_in[i];
    }
    float* out = (float*)d_out;

    tysq_kernel<<<(M_TGT + 255) / 256, 256>>>(Y);
    prep_kernel<<<1, 256>>>(psi);

    cudaFuncSetAttribute(lse_mma_kernel,
                         cudaFuncAttributeMaxDynamicSharedMemorySize, SM_TOTAL);
    lse_mma_kernel<<<N_SRC / BM, NT, SM_TOTAL>>>(X, Y, out);
}

// round 6
// speedup vs baseline: 4.3099x; 1.3047x over previous
#include <cuda_runtime.h>
#include <cuda_fp16.h>
#include <math.h>
#include <cstdint>

#define N_SRC 32768
#define M_TGT 8192
#define D_DIM 64
#define REG_P 0.01f
#define INV_REG 100.0f
#define LOG2E 1.4426950408889634f
#define LN2 0.6931471805599453f

#define BM 128
#define BN 128
#define NT 256
#define NTILES (M_TGT / BN)   // 64
#define NSTAGE 4

// ---------------- scratch ----------------
__device__ float  g_tysq[M_TGT];
__device__ float  g_c2[M_TGT];      // (psi - tysq/mv) * INV_REG * LOG2E
__device__ float  g_scalars[4];     // 0: 1/mv, 1: 2*invmv*INV_REG*LOG2E, 2: mean(psi)
__device__ __half g_Xh[N_SRC * D_DIM];   // fp16 copies (rn)
__device__ __half g_Yh[M_TGT * D_DIM];

// ---------------- helpers ----------------
__device__ __forceinline__ uint32_t smem_u32(const void* p) {
    uint32_t a;
    asm("{ .reg .u64 t; cvta.to.shared.u64 t, %1; cvt.u32.u64 %0, t; }" : "=r"(a) : "l"(p));
    return a;
}
__device__ __forceinline__ uint64_t gmem_u64(const void* p) {
    uint64_t a;
    asm("cvta.to.global.u64 %0, %1;" : "=l"(a) : "l"(p));
    return a;
}
__device__ __forceinline__ float ex2f(float x) {
    float r; asm("ex2.approx.ftz.f32 %0, %1;" : "=f"(r) : "f"(x)); return r;
}
__device__ __forceinline__ float lg2f(float x) {
    float r; asm("lg2.approx.f32 %0, %1;" : "=f"(r) : "f"(x)); return r;
}

#define CP_ASYNC16(s, g) \
    asm volatile("cp.async.cg.shared.global [%0], [%1], 16;" :: "r"(s), "l"(g))
#define CP_COMMIT() asm volatile("cp.async.commit_group;" ::: "memory")
#define CP_WAIT(n)  asm volatile("cp.async.wait_group %0;" :: "n"(n) : "memory")

__device__ __forceinline__ void ldsm4(uint32_t* r, uint32_t addr) {
    asm volatile("ldmatrix.sync.aligned.m8n8.x4.shared.b16 {%0,%1,%2,%3}, [%4];"
                 : "=r"(r[0]), "=r"(r[1]), "=r"(r[2]), "=r"(r[3]) : "r"(addr));
}
__device__ __forceinline__ void mma_f16(float* c, const uint32_t* a,
                                        uint32_t b0, uint32_t b1) {
    asm volatile("mma.sync.aligned.m16n8k16.row.col.f32.f16.f16.f32 "
                 "{%0,%1,%2,%3}, {%4,%5,%6,%7}, {%8,%9}, {%0,%1,%2,%3};"
                 : "+f"(c[0]), "+f"(c[1]), "+f"(c[2]), "+f"(c[3])
                 : "r"(a[0]), "r"(a[1]), "r"(a[2]), "r"(a[3]), "r"(b0), "r"(b1));
}

// smem layout (bytes): Xh 16KB | Yh 4x16KB | cs 4x512B
#define SM_X 0
#define SM_Y 16384
#define SM_C (16384 + 65536)
#define SM_TOTAL (SM_C + 2048)      // 83968

// ---------------- kernel A: per-target squared norms (fp32 exact) ----------------
__global__ void tysq_kernel(const float* __restrict__ Y) {
    int m = blockIdx.x * blockDim.x + threadIdx.x;
    if (m >= M_TGT) return;
    const float4* row = reinterpret_cast<const float4*>(Y + (size_t)m * D_DIM);
    float acc = 0.f;
#pragma unroll
    for (int i = 0; i < D_DIM / 4; i++) {
        float4 v = row[i];
        acc += v.x * v.x + v.y * v.y + v.z * v.z + v.w * v.w;
    }
    g_tysq[m] = acc;
}

// ---------------- kernel A2: fp32 -> fp16 conversion ----------------
__global__ void conv_kernel(const float* __restrict__ src, __half* dst, int n2) {
    int i = blockIdx.x * blockDim.x + threadIdx.x;   // over half2
    if (i >= n2) return;
    float2 v = reinterpret_cast<const float2*>(src)[i];
    reinterpret_cast<__half2*>(dst)[i] = __float22half2_rn(v);
}

// ---------------- kernel B: deterministic reductions + c2[m] ----------------
__global__ void prep_kernel(const float* __restrict__ psi) {
    __shared__ float red_t[256];
    __shared__ float red_p[256];
    __shared__ float inv_mv_s;
    int t = threadIdx.x;
    float st = 0.f, sp = 0.f;
    for (int m = t; m < M_TGT; m += 256) { st += g_tysq[m]; sp += psi[m]; }
    red_t[t] = st; red_p[t] = sp;
    __syncthreads();
    for (int off = 128; off > 0; off >>= 1) {
        if (t < off) { red_t[t] += red_t[t + off]; red_p[t] += red_p[t + off]; }
        __syncthreads();
    }
    if (t == 0) {
        float mv = red_t[0] / (float)M_TGT;
        float inv_mv = 1.0f / mv;
        g_scalars[0] = inv_mv;
        g_scalars[1] = 2.0f * inv_mv * INV_REG * LOG2E;
        g_scalars[2] = red_p[0] / (float)M_TGT;
        inv_mv_s = inv_mv;
    }
    __syncthreads();
    float inv_mv = inv_mv_s;
    for (int m = t; m < M_TGT; m += 256)
        g_c2[m] = (psi[m] - g_tysq[m] * inv_mv) * (INV_REG * LOG2E);
}

// ---------------- main kernel ----------------
extern __shared__ char smem[];

__global__ __launch_bounds__(NT, 1)
void lse_mma_kernel(const float* __restrict__ X, float* __restrict__ out) {
    const uint32_t sb = smem_u32(smem);
    const int tid  = threadIdx.x;
    const int lane = tid & 31;
    const int wid  = tid >> 5;
    const int mwarp = wid >> 1;          // 0..3 -> rows mwarp*32..+31
    const int nwarp = wid & 1;           // 0..1 -> cols nwarp*64..+63
    const int q  = lane & 3;
    const int g4 = lane >> 2;
    const int rowBase = blockIdx.x * BM;

    const float invmv = g_scalars[0];
    const float s2    = g_scalars[1];
    const float mpsi  = g_scalars[2];

    const uint64_t Yg = gmem_u64(g_Yh);     // fp16, 128B per row
    const uint64_t Xg = gmem_u64(g_Xh);
    const uint64_t Cg = gmem_u64(g_c2);

    // ---- prefetch Y tiles 0..2 (fp16: 16KB = 1024 x 16B chunks per tile) ----
#pragma unroll
    for (int pt = 0; pt < NSTAGE - 1; pt++) {
#pragma unroll
        for (int i = 0; i < 4; i++) {
            int idx = tid + i * NT;
            int row = idx >> 3, ch = idx & 7;
            uint32_t s = sb + SM_Y + pt * 16384 + row * 128 + ((ch ^ (row & 7)) << 4);
            uint64_t g = Yg + (uint64_t)(pt * BN + row) * 128 + ch * 16;
            CP_ASYNC16(s, g);
        }
        if (tid < 32) {
            uint32_t s = sb + SM_C + pt * 512 + tid * 16;
            uint64_t g = Cg + (uint64_t)(pt * BN + tid * 4) * 4;
            CP_ASYNC16(s, g);
        }
        CP_COMMIT();
    }

    // ---- X tile (fp16) -> smem ----
#pragma unroll
    for (int i = 0; i < 4; i++) {
        int idx = tid + i * NT;
        int row = idx >> 3, ch = idx & 7;
        uint4 v = *reinterpret_cast<const uint4*>(
            reinterpret_cast<const char*>(g_Xh) + (uint64_t)(rowBase + row) * 128 + ch * 16);
        *reinterpret_cast<uint4*>(smem + SM_X + row * 128 + ((ch ^ (row & 7)) << 4)) = v;
    }
    (void)Xg;
    __syncthreads();

    // ---- A fragments (fp16, register-resident): A[mt][ks] = 4 regs ----
    uint32_t A[2][4][4];
    {
        const int b = lane >> 3, lr = lane & 7;
        const int rsel = (b & 1) * 8, csel = b >> 1;      // csel in {0,1}
#pragma unroll
        for (int mt = 0; mt < 2; mt++)
#pragma unroll
            for (int ks = 0; ks < 4; ks++) {
                int row = mwarp * 32 + mt * 16 + rsel + lr;
                int ch  = ks * 2 + csel;
                uint32_t ad = sb + SM_X + row * 128 + ((ch ^ lr) << 4);
                ldsm4(A[mt][ks], ad);
            }
    }

    const int bB = lane >> 3, lrB = lane & 7;
    const int rselB = (bB >> 1) * 8, cselB = bB & 1;

    float runm[4], runs[4];
#pragma unroll
    for (int r = 0; r < 4; r++) { runm[r] = -INFINITY; runs[r] = 0.f; }

    for (int t = 0; t < NTILES; t++) {
        CP_WAIT(2);
        __syncthreads();
        const int buf = t & (NSTAGE - 1);
        const uint32_t yb = sb + SM_Y + buf * 16384;

        if (t + NSTAGE - 1 < NTILES) {
            const int ft = t + NSTAGE - 1;
            const int fb = ft & (NSTAGE - 1);
#pragma unroll
            for (int i = 0; i < 4; i++) {
                int idx = tid + i * NT;
                int row = idx >> 3, ch = idx & 7;
                uint32_t s = sb + SM_Y + fb * 16384 + row * 128 + ((ch ^ (row & 7)) << 4);
                uint64_t g = Yg + (uint64_t)(ft * BN + row) * 128 + ch * 16;
                CP_ASYNC16(s, g);
            }
            if (tid < 32) {
                uint32_t s = sb + SM_C + fb * 512 + tid * 16;
                uint64_t g = Cg + (uint64_t)(ft * BN + tid * 4) * 4;
                CP_ASYNC16(s, g);
            }
        }
        CP_COMMIT();

        // c fragments early
        float2 cpv[8];
        {
            const float* cbB = reinterpret_cast<const float*>(smem + SM_C + buf * 512)
                               + nwarp * 64;
#pragma unroll
            for (int nt = 0; nt < 8; nt++)
                cpv[nt] = *reinterpret_cast<const float2*>(cbB + nt * 8 + q * 2);
        }

        float acc[2][8][4];
#pragma unroll
        for (int mt = 0; mt < 2; mt++)
#pragma unroll
            for (int nt = 0; nt < 8; nt++)
#pragma unroll
                for (int j = 0; j < 4; j++) acc[mt][nt][j] = 0.f;

#pragma unroll
        for (int nt2 = 0; nt2 < 4; nt2++) {
            const uint32_t rowb =
                yb + (uint32_t)(nwarp * 64 + nt2 * 16 + rselB + lrB) * 128;
#pragma unroll
            for (int ks = 0; ks < 4; ks++) {
                uint32_t B[4];   // B0=(n0,k0-7) B1=(n0,k8-15) B2=(n8,k0-7) B3=(n8,k8-15)
                uint32_t ad = rowb + (((ks * 2 + cselB) ^ lrB) << 4);
                ldsm4(B, ad);
#pragma unroll
                for (int mt = 0; mt < 2; mt++) {
                    mma_f16(acc[mt][nt2 * 2 + 0], A[mt][ks], B[0], B[1]);
                    mma_f16(acc[mt][nt2 * 2 + 1], A[mt][ks], B[2], B[3]);
                }
            }
        }

        // ---- fused epilogue: v = c + s2*dot (log2 domain), online lse ----
#pragma unroll
        for (int mt = 0; mt < 2; mt++) {
            float vA[16], vB[16];
            float mA = -INFINITY, mB = -INFINITY;
#pragma unroll
            for (int nt = 0; nt < 8; nt++) {
                float a0 = fmaf(s2, acc[mt][nt][0], cpv[nt].x);
                float a1 = fmaf(s2, acc[mt][nt][1], cpv[nt].y);
                float b0 = fmaf(s2, acc[mt][nt][2], cpv[nt].x);
                float b1 = fmaf(s2, acc[mt][nt][3], cpv[nt].y);
                vA[nt * 2] = a0; vA[nt * 2 + 1] = a1;
                vB[nt * 2] = b0; vB[nt * 2 + 1] = b1;
                mA = fmaxf(mA, fmaxf(a0, a1));
                mB = fmaxf(mB, fmaxf(b0, b1));
            }
            const int r0 = mt * 2, r1 = mt * 2 + 1;
            if (mA > runm[r0] - 20.f) {
                if (mA > runm[r0]) { runs[r0] *= ex2f(runm[r0] - mA); runm[r0] = mA; }
                float s0 = 0.f, s1 = 0.f;
#pragma unroll
                for (int j = 0; j < 16; j += 2) {
                    s0 += ex2f(vA[j]     - runm[r0]);
                    s1 += ex2f(vA[j + 1] - runm[r0]);
                }
                runs[r0] += s0 + s1;
            }
            if (mB > runm[r1] - 20.f) {
                if (mB > runm[r1]) { runs[r1] *= ex2f(runm[r1] - mB); runm[r1] = mB; }
                float s0 = 0.f, s1 = 0.f;
#pragma unroll
                for (int j = 0; j < 16; j += 2) {
                    s0 += ex2f(vB[j]     - runm[r1]);
                    s1 += ex2f(vB[j + 1] - runm[r1]);
                }
                runs[r1] += s0 + s1;
            }
        }
    }

    // ---- reduce across the 4 lanes sharing each row ----
    float fm[4], fs[4];
#pragma unroll
    for (int r = 0; r < 4; r++) {
        float m = runm[r], s = runs[r];
#pragma unroll
        for (int off = 1; off < 4; off <<= 1) {
            float m2 = __shfl_xor_sync(0xffffffffu, m, off);
            float s2x = __shfl_xor_sync(0xffffffffu, s, off);
            float nm = fmaxf(m, m2);
            s = s * ex2f(m - nm) + s2x * ex2f(m2 - nm);
            m = nm;
        }
        fm[r] = m; fs[r] = s;
    }

    __syncthreads();
    float* pm = reinterpret_cast<float*>(smem);   // [2][128]
    float* ps = pm + 256;
    if (q == 0) {
#pragma unroll
        for (int r = 0; r < 4; r++) {
            int mt = r >> 1, hf = r & 1;
            int rl = mwarp * 32 + mt * 16 + hf * 8 + g4;
            pm[nwarp * 128 + rl] = fm[r];
            ps[nwarp * 128 + rl] = fs[r];
        }
    }
    __syncthreads();
    if (tid < BM) {
        float ma = pm[tid], mb = pm[128 + tid];
        float sa = ps[tid], sb2 = ps[128 + tid];
        float mM = fmaxf(ma, mb);
        float ss = sa * ex2f(ma - mM) + sb2 * ex2f(mb - mM);
        const float4* xr = reinterpret_cast<const float4*>(
            X + (size_t)(rowBase + tid) * D_DIM);
        float xs = 0.f;
#pragma unroll
        for (int i = 0; i < 16; i++) {
            float4 v = xr[i];
            xs = fmaf(v.x, v.x, fmaf(v.y, v.y, fmaf(v.z, v.z, fmaf(v.w, v.w, xs))));
        }
        out[rowBase + tid] = fmaf(xs, invmv, mpsi) - (REG_P * LN2) * (mM + lg2f(ss));
    }
}

// ---------------- launch ----------------
extern "C" void kernel_launch(void* const* d_in, const int* in_sizes, int n_in,
                              void* d_out, int out_size) {
    const float *X = nullptr, *Y = nullptr, *psi = nullptr;
    for (int i = 0; i < n_in; i++) {
        if (in_sizes[i] == N_SRC * D_DIM)      X   = (const float*)d_in[i];
        else if (in_sizes[i] == M_TGT * D_DIM) Y   = (const float*)d_in[i];
        else if (in_sizes[i] == M_TGT)         psi = (const float*)d_in[i];
    }
    float* out = (float*)d_out;

    __half* xh; cudaGetSymbolAddress((void**)&xh, g_Xh);
    __half* yh; cudaGetSymbolAddress((void**)&yh, g_Yh);

    tysq_kernel<<<(M_TGT + 255) / 256, 256>>>(Y);
    conv_kernel<<<(N_SRC * D_DIM / 2 + 255) / 256, 256>>>(X, xh, N_SRC * D_DIM / 2);
    conv_kernel<<<(M_TGT * D_DIM / 2 + 255) / 256, 256>>>(Y, yh, M_TGT * D_DIM / 2);
    prep_kernel<<<1, 256>>>(psi);

    cudaFuncSetAttribute(lse_mma_kernel,
                         cudaFuncAttributeMaxDynamicSharedMemorySize, SM_TOTAL);
    lse_mma_kernel<<<N_SRC / BM, NT, SM_TOTAL>>>(X, out);
}

// round 7
// speedup vs baseline: 4.7404x; 1.0999x over previous
#include <cuda_runtime.h>
#include <cuda_fp16.h>
#include <math.h>
#include <cstdint>

#define N_SRC 32768
#define M_TGT 8192
#define D_DIM 64
#define REG_P 0.01f
#define INV_REG 100.0f
#define LOG2E 1.4426950408889634f
#define LN2 0.6931471805599453f

#define BM 128
#define BN 128
#define NT 256
#define GRID 148
#define NRB (N_SRC / BM)        // 256 row-blocks
#define NCHUNK 4
#define TPC 16                  // tiles per chunk (64 total / 4)
#define NJOBS (NRB * NCHUNK)    // 1024
#define NSTAGE 4

// ---------------- scratch ----------------
__device__ float  g_tysq[M_TGT];
__device__ float  g_c2[M_TGT];       // (psi - tysq/mv) * INV_REG * LOG2E
__device__ float  g_scalars[4];      // 0: 1/mv, 1: 2*invmv*INV_REG*LOG2E, 2: mean(psi)
__device__ __half g_Xh[N_SRC * D_DIM];
__device__ __half g_Yh[M_TGT * D_DIM];
__device__ float  g_pm[NRB * NCHUNK * 2 * BM];   // partial max  [rb][ck][nwarp][row]
__device__ float  g_ps[NRB * NCHUNK * 2 * BM];   // partial sum

// ---------------- helpers ----------------
__device__ __forceinline__ uint32_t smem_u32(const void* p) {
    uint32_t a;
    asm("{ .reg .u64 t; cvta.to.shared.u64 t, %1; cvt.u32.u64 %0, t; }" : "=r"(a) : "l"(p));
    return a;
}
__device__ __forceinline__ uint64_t gmem_u64(const void* p) {
    uint64_t a;
    asm("cvta.to.global.u64 %0, %1;" : "=l"(a) : "l"(p));
    return a;
}
__device__ __forceinline__ float ex2f(float x) {
    float r; asm("ex2.approx.ftz.f32 %0, %1;" : "=f"(r) : "f"(x)); return r;
}
__device__ __forceinline__ float lg2f(float x) {
    float r; asm("lg2.approx.f32 %0, %1;" : "=f"(r) : "f"(x)); return r;
}

#define CP_ASYNC16(s, g) \
    asm volatile("cp.async.cg.shared.global [%0], [%1], 16;" :: "r"(s), "l"(g))
#define CP_COMMIT() asm volatile("cp.async.commit_group;" ::: "memory")
#define CP_WAIT(n)  asm volatile("cp.async.wait_group %0;" :: "n"(n) : "memory")

__device__ __forceinline__ void ldsm4(uint32_t* r, uint32_t addr) {
    asm volatile("ldmatrix.sync.aligned.m8n8.x4.shared.b16 {%0,%1,%2,%3}, [%4];"
                 : "=r"(r[0]), "=r"(r[1]), "=r"(r[2]), "=r"(r[3]) : "r"(addr));
}
__device__ __forceinline__ void mma_f16(float* c, const uint32_t* a,
                                        uint32_t b0, uint32_t b1) {
    asm volatile("mma.sync.aligned.m16n8k16.row.col.f32.f16.f16.f32 "
                 "{%0,%1,%2,%3}, {%4,%5,%6,%7}, {%8,%9}, {%0,%1,%2,%3};"
                 : "+f"(c[0]), "+f"(c[1]), "+f"(c[2]), "+f"(c[3])
                 : "r"(a[0]), "r"(a[1]), "r"(a[2]), "r"(a[3]), "r"(b0), "r"(b1));
}

// smem layout (bytes): Xh 16KB | Yh 4x16KB | cs 4x512B
#define SM_X 0
#define SM_Y 16384
#define SM_C (16384 + 65536)
#define SM_TOTAL (SM_C + 2048)      // 83968

// ---------------- kernel A: fp32 -> fp16 (X) ----------------
__global__ void convX_kernel(const float* __restrict__ src) {
    int i = blockIdx.x * blockDim.x + threadIdx.x;
    if (i >= N_SRC * D_DIM / 2) return;
    float2 v = reinterpret_cast<const float2*>(src)[i];
    reinterpret_cast<__half2*>(g_Xh)[i] = __float22half2_rn(v);
}

// ---------------- kernel B: fused Y convert + row norms (8 lanes / row) ---------
__global__ void convY_tysq_kernel(const float* __restrict__ Y) {
    int gid = blockIdx.x * blockDim.x + threadIdx.x;     // 65536 threads
    int r = gid >> 3, c8 = gid & 7;
    const float4* p = reinterpret_cast<const float4*>(Y + (size_t)r * D_DIM + c8 * 8);
    float4 v0 = p[0], v1 = p[1];
    __half2 h[4];
    h[0] = __float22half2_rn(make_float2(v0.x, v0.y));
    h[1] = __float22half2_rn(make_float2(v0.z, v0.w));
    h[2] = __float22half2_rn(make_float2(v1.x, v1.y));
    h[3] = __float22half2_rn(make_float2(v1.z, v1.w));
    *reinterpret_cast<uint4*>(g_Yh + (size_t)r * D_DIM + c8 * 8) =
        *reinterpret_cast<uint4*>(h);
    float s = v0.x * v0.x + v0.y * v0.y + v0.z * v0.z + v0.w * v0.w
            + v1.x * v1.x + v1.y * v1.y + v1.z * v1.z + v1.w * v1.w;
    s += __shfl_down_sync(0xffffffffu, s, 4, 8);
    s += __shfl_down_sync(0xffffffffu, s, 2, 8);
    s += __shfl_down_sync(0xffffffffu, s, 1, 8);
    if (c8 == 0) g_tysq[r] = s;
}

// ---------------- kernel C: deterministic reductions + c2[m] ----------------
__global__ void prep_kernel(const float* __restrict__ psi) {
    __shared__ float red_t[1024];
    __shared__ float red_p[1024];
    __shared__ float inv_mv_s;
    int t = threadIdx.x;
    float st = 0.f, sp = 0.f;
    for (int m = t; m < M_TGT; m += 1024) { st += g_tysq[m]; sp += psi[m]; }
    red_t[t] = st; red_p[t] = sp;
    __syncthreads();
    for (int off = 512; off > 0; off >>= 1) {
        if (t < off) { red_t[t] += red_t[t + off]; red_p[t] += red_p[t + off]; }
        __syncthreads();
    }
    if (t == 0) {
        float mv = red_t[0] / (float)M_TGT;
        float inv_mv = 1.0f / mv;
        g_scalars[0] = inv_mv;
        g_scalars[1] = 2.0f * inv_mv * INV_REG * LOG2E;
        g_scalars[2] = red_p[0] / (float)M_TGT;
        inv_mv_s = inv_mv;
    }
    __syncthreads();
    float inv_mv = inv_mv_s;
    for (int m = t; m < M_TGT; m += 1024)
        g_c2[m] = (psi[m] - g_tysq[m] * inv_mv) * (INV_REG * LOG2E);
}

// ---------------- main kernel: persistent jobs ----------------
extern __shared__ char smem[];

__global__ __launch_bounds__(NT, 1)
void lse_mma_kernel() {
    const uint32_t sb = smem_u32(smem);
    const int tid  = threadIdx.x;
    const int lane = tid & 31;
    const int wid  = tid >> 5;
    const int mwarp = wid >> 1;          // 0..3 -> rows mwarp*32..+31
    const int nwarp = wid & 1;           // 0..1 -> cols nwarp*64..+63
    const int q  = lane & 3;
    const int g4 = lane >> 2;

    const float s2 = g_scalars[1];

    const uint64_t Yg = gmem_u64(g_Yh);
    const uint64_t Cg = gmem_u64(g_c2);

    const int b = lane >> 3, lr = lane & 7;
    const int rselA = (b & 1) * 8, cselA = b >> 1;
    const int rselB = (b >> 1) * 8, cselB = b & 1;

    for (int job = blockIdx.x; job < NJOBS; job += GRID) {
        const int rb = job >> 2;
        const int ck = job & 3;
        const int rowBase = rb * BM;
        const int tile0 = ck * TPC;

        __syncthreads();   // all warps done with previous job's smem

        // ---- X tile (fp16) -> smem ----
#pragma unroll
        for (int i = 0; i < 4; i++) {
            int idx = tid + i * NT;
            int row = idx >> 3, ch = idx & 7;
            uint4 v = *reinterpret_cast<const uint4*>(
                reinterpret_cast<const char*>(g_Xh) +
                (uint64_t)(rowBase + row) * 128 + ch * 16);
            *reinterpret_cast<uint4*>(smem + SM_X + row * 128 +
                                      ((ch ^ (row & 7)) << 4)) = v;
        }
        // ---- prefetch Y tiles tile0..tile0+2 ----
#pragma unroll
        for (int pt = 0; pt < NSTAGE - 1; pt++) {
#pragma unroll
            for (int i = 0; i < 4; i++) {
                int idx = tid + i * NT;
                int row = idx >> 3, ch = idx & 7;
                uint32_t s = sb + SM_Y + pt * 16384 + row * 128 + ((ch ^ (row & 7)) << 4);
                uint64_t g = Yg + (uint64_t)((tile0 + pt) * BN + row) * 128 + ch * 16;
                CP_ASYNC16(s, g);
            }
            if (tid < 32) {
                uint32_t s = sb + SM_C + pt * 512 + tid * 16;
                uint64_t g = Cg + (uint64_t)((tile0 + pt) * BN + tid * 4) * 4;
                CP_ASYNC16(s, g);
            }
            CP_COMMIT();
        }
        __syncthreads();   // X visible

        // ---- A fragments ----
        uint32_t A[2][4][4];
#pragma unroll
        for (int mt = 0; mt < 2; mt++)
#pragma unroll
            for (int ks = 0; ks < 4; ks++) {
                int row = mwarp * 32 + mt * 16 + rselA + lr;
                int ch  = ks * 2 + cselA;
                ldsm4(A[mt][ks], sb + SM_X + row * 128 + ((ch ^ lr) << 4));
            }

        float runm[4], runs[4];
#pragma unroll
        for (int r = 0; r < 4; r++) { runm[r] = -INFINITY; runs[r] = 0.f; }

        for (int t = 0; t < TPC; t++) {
            CP_WAIT(2);
            __syncthreads();
            const int buf = t & (NSTAGE - 1);
            const uint32_t yb = sb + SM_Y + buf * 16384;

            if (t + NSTAGE - 1 < TPC) {
                const int ft = t + NSTAGE - 1;
                const int fb = ft & (NSTAGE - 1);
#pragma unroll
                for (int i = 0; i < 4; i++) {
                    int idx = tid + i * NT;
                    int row = idx >> 3, ch = idx & 7;
                    uint32_t s = sb + SM_Y + fb * 16384 + row * 128 +
                                 ((ch ^ (row & 7)) << 4);
                    uint64_t g = Yg + (uint64_t)((tile0 + ft) * BN + row) * 128 + ch * 16;
                    CP_ASYNC16(s, g);
                }
                if (tid < 32) {
                    uint32_t s = sb + SM_C + fb * 512 + tid * 16;
                    uint64_t g = Cg + (uint64_t)((tile0 + ft) * BN + tid * 4) * 4;
                    CP_ASYNC16(s, g);
                }
            }
            CP_COMMIT();

            float2 cpv[8];
            {
                const float* cbB = reinterpret_cast<const float*>(smem + SM_C + buf * 512)
                                   + nwarp * 64;
#pragma unroll
                for (int nt = 0; nt < 8; nt++)
                    cpv[nt] = *reinterpret_cast<const float2*>(cbB + nt * 8 + q * 2);
            }

            float acc[2][8][4];
#pragma unroll
            for (int mt = 0; mt < 2; mt++)
#pragma unroll
                for (int nt = 0; nt < 8; nt++)
#pragma unroll
                    for (int j = 0; j < 4; j++) acc[mt][nt][j] = 0.f;

#pragma unroll
            for (int nt2 = 0; nt2 < 4; nt2++) {
                const uint32_t rowb =
                    yb + (uint32_t)(nwarp * 64 + nt2 * 16 + rselB + lr) * 128;
#pragma unroll
                for (int ks = 0; ks < 4; ks++) {
                    uint32_t B[4];
                    ldsm4(B, rowb + (((ks * 2 + cselB) ^ lr) << 4));
#pragma unroll
                    for (int mt = 0; mt < 2; mt++) {
                        mma_f16(acc[mt][nt2 * 2 + 0], A[mt][ks], B[0], B[1]);
                        mma_f16(acc[mt][nt2 * 2 + 1], A[mt][ks], B[2], B[3]);
                    }
                }
            }

            // ---- fused epilogue: online log2-sum-exp2 ----
#pragma unroll
            for (int mt = 0; mt < 2; mt++) {
                float vA[16], vB[16];
                float mA = -INFINITY, mB = -INFINITY;
#pragma unroll
                for (int nt = 0; nt < 8; nt++) {
                    float a0 = fmaf(s2, acc[mt][nt][0], cpv[nt].x);
                    float a1 = fmaf(s2, acc[mt][nt][1], cpv[nt].y);
                    float b0 = fmaf(s2, acc[mt][nt][2], cpv[nt].x);
                    float b1 = fmaf(s2, acc[mt][nt][3], cpv[nt].y);
                    vA[nt * 2] = a0; vA[nt * 2 + 1] = a1;
                    vB[nt * 2] = b0; vB[nt * 2 + 1] = b1;
                    mA = fmaxf(mA, fmaxf(a0, a1));
                    mB = fmaxf(mB, fmaxf(b0, b1));
                }
                const int r0 = mt * 2, r1 = mt * 2 + 1;
                if (mA > runm[r0] - 20.f) {
                    if (mA > runm[r0]) { runs[r0] *= ex2f(runm[r0] - mA); runm[r0] = mA; }
                    float s0 = 0.f, s1 = 0.f;
#pragma unroll
                    for (int j = 0; j < 16; j += 2) {
                        s0 += ex2f(vA[j]     - runm[r0]);
                        s1 += ex2f(vA[j + 1] - runm[r0]);
                    }
                    runs[r0] += s0 + s1;
                }
                if (mB > runm[r1] - 20.f) {
                    if (mB > runm[r1]) { runs[r1] *= ex2f(runm[r1] - mB); runm[r1] = mB; }
                    float s0 = 0.f, s1 = 0.f;
#pragma unroll
                    for (int j = 0; j < 16; j += 2) {
                        s0 += ex2f(vB[j]     - runm[r1]);
                        s1 += ex2f(vB[j + 1] - runm[r1]);
                    }
                    runs[r1] += s0 + s1;
                }
            }
        }

        // ---- merge across the 4 lanes sharing each row; write partials ----
#pragma unroll
        for (int r = 0; r < 4; r++) {
            float m = runm[r], s = runs[r];
#pragma unroll
            for (int off = 1; off < 4; off <<= 1) {
                float m2 = __shfl_xor_sync(0xffffffffu, m, off);
                float s2x = __shfl_xor_sync(0xffffffffu, s, off);
                float nm = fmaxf(m, m2);
                s = s * ex2f(m - nm) + s2x * ex2f(m2 - nm);
                m = nm;
            }
            if (q == 0) {
                int mt = r >> 1, hf = r & 1;
                int rl = mwarp * 32 + mt * 16 + hf * 8 + g4;
                int idx = ((rb * NCHUNK + ck) * 2 + nwarp) * BM + rl;
                g_pm[idx] = m;
                g_ps[idx] = s;
            }
        }
    }
}

// ---------------- finalize: merge 8 partials/row, add norms, write out --------
__global__ void final_kernel(const float* __restrict__ X, float* __restrict__ out) {
    int r = blockIdx.x * blockDim.x + threadIdx.x;
    if (r >= N_SRC) return;
    int rb = r >> 7, rl = r & 127;
    const float invmv = g_scalars[0];
    const float mpsi  = g_scalars[2];
    float m = -INFINITY, s = 0.f;
#pragma unroll
    for (int ck = 0; ck < NCHUNK; ck++)
#pragma unroll
        for (int nw = 0; nw < 2; nw++) {
            int idx = ((rb * NCHUNK + ck) * 2 + nw) * BM + rl;
            float m2 = g_pm[idx], s2v = g_ps[idx];
            float nm = fmaxf(m, m2);
            s = s * ex2f(m - nm) + s2v * ex2f(m2 - nm);
            m = nm;
        }
    const float4* xr = reinterpret_cast<const float4*>(X + (size_t)r * D_DIM);
    float xs = 0.f;
#pragma unroll
    for (int i = 0; i < 16; i++) {
        float4 v = xr[i];
        xs = fmaf(v.x, v.x, fmaf(v.y, v.y, fmaf(v.z, v.z, fmaf(v.w, v.w, xs))));
    }
    out[r] = fmaf(xs, invmv, mpsi) - (REG_P * LN2) * (m + lg2f(s));
}

// ---------------- launch ----------------
extern "C" void kernel_launch(void* const* d_in, const int* in_sizes, int n_in,
                              void* d_out, int out_size) {
    const float *X = nullptr, *Y = nullptr, *psi = nullptr;
    for (int i = 0; i < n_in; i++) {
        if (in_sizes[i] == N_SRC * D_DIM)      X   = (const float*)d_in[i];
        else if (in_sizes[i] == M_TGT * D_DIM) Y   = (const float*)d_in[i];
        else if (in_sizes[i] == M_TGT)         psi = (const float*)d_in[i];
    }
    float* out = (float*)d_out;

    convX_kernel<<<(N_SRC * D_DIM / 2 + 255) / 256, 256>>>(X);
    convY_tysq_kernel<<<(M_TGT * 8) / 256, 256>>>(Y);
    prep_kernel<<<1, 1024>>>(psi);

    cudaFuncSetAttribute(lse_mma_kernel,
                         cudaFuncAttributeMaxDynamicSharedMemorySize, SM_TOTAL);
    lse_mma_kernel<<<GRID, NT, SM_TOTAL>>>();

    final_kernel<<<N_SRC / 256, 256>>>(X, out);
}

// round 8
// speedup vs baseline: 4.7893x; 1.0103x over previous
#include <cuda_runtime.h>
#include <cuda_fp16.h>
#include <math.h>
#include <cstdint>

#define N_SRC 32768
#define M_TGT 8192
#define D_DIM 64
#define REG_P 0.01f
#define INV_REG 100.0f
#define LOG2E 1.4426950408889634f
#define LN2 0.6931471805599453f

#define BM 128
#define BN 128
#define NT 512
#define GRID 148
#define NRB (N_SRC / BM)        // 256 row-blocks
#define NCHUNK 4
#define TPC 16                  // tiles per chunk
#define NJOBS (NRB * NCHUNK)    // 1024
#define NSTAGE 4

// ---------------- scratch ----------------
__device__ float  g_tysq[M_TGT];
__device__ float  g_c2[M_TGT];
__device__ float  g_scalars[4];      // 0: 1/mv, 1: 2*invmv*INV_REG*LOG2E, 2: mean(psi)
__device__ __half g_Xh[N_SRC * D_DIM];
__device__ __half g_Yh[M_TGT * D_DIM];
__device__ float  g_pm[NRB * NCHUNK * 4 * BM];   // [rb][ck][nwarp][row]
__device__ float  g_ps[NRB * NCHUNK * 4 * BM];

// ---------------- helpers ----------------
__device__ __forceinline__ uint32_t smem_u32(const void* p) {
    uint32_t a;
    asm("{ .reg .u64 t; cvta.to.shared.u64 t, %1; cvt.u32.u64 %0, t; }" : "=r"(a) : "l"(p));
    return a;
}
__device__ __forceinline__ uint64_t gmem_u64(const void* p) {
    uint64_t a;
    asm("cvta.to.global.u64 %0, %1;" : "=l"(a) : "l"(p));
    return a;
}
__device__ __forceinline__ float ex2f(float x) {
    float r; asm("ex2.approx.ftz.f32 %0, %1;" : "=f"(r) : "f"(x)); return r;
}
__device__ __forceinline__ float lg2f(float x) {
    float r; asm("lg2.approx.f32 %0, %1;" : "=f"(r) : "f"(x)); return r;
}

#define CP_ASYNC16(s, g) \
    asm volatile("cp.async.cg.shared.global [%0], [%1], 16;" :: "r"(s), "l"(g))
#define CP_COMMIT() asm volatile("cp.async.commit_group;" ::: "memory")
#define CP_WAIT(n)  asm volatile("cp.async.wait_group %0;" :: "n"(n) : "memory")

__device__ __forceinline__ void ldsm4(uint32_t* r, uint32_t addr) {
    asm volatile("ldmatrix.sync.aligned.m8n8.x4.shared.b16 {%0,%1,%2,%3}, [%4];"
                 : "=r"(r[0]), "=r"(r[1]), "=r"(r[2]), "=r"(r[3]) : "r"(addr));
}
__device__ __forceinline__ void mma_f16(float* c, const uint32_t* a,
                                        uint32_t b0, uint32_t b1) {
    asm volatile("mma.sync.aligned.m16n8k16.row.col.f32.f16.f16.f32 "
                 "{%0,%1,%2,%3}, {%4,%5,%6,%7}, {%8,%9}, {%0,%1,%2,%3};"
                 : "+f"(c[0]), "+f"(c[1]), "+f"(c[2]), "+f"(c[3])
                 : "r"(a[0]), "r"(a[1]), "r"(a[2]), "r"(a[3]), "r"(b0), "r"(b1));
}

// smem layout (bytes): Xh 16KB | Yh 4x16KB | cs 4x512B
#define SM_X 0
#define SM_Y 16384
#define SM_C (16384 + 65536)
#define SM_TOTAL (SM_C + 2048)      // 83968

// ---------------- prologue kernels ----------------
__global__ void convX_kernel(const float* __restrict__ src) {
    int i = blockIdx.x * blockDim.x + threadIdx.x;
    if (i >= N_SRC * D_DIM / 2) return;
    float2 v = reinterpret_cast<const float2*>(src)[i];
    reinterpret_cast<__half2*>(g_Xh)[i] = __float22half2_rn(v);
}

__global__ void convY_tysq_kernel(const float* __restrict__ Y) {
    int gid = blockIdx.x * blockDim.x + threadIdx.x;
    int r = gid >> 3, c8 = gid & 7;
    const float4* p = reinterpret_cast<const float4*>(Y + (size_t)r * D_DIM + c8 * 8);
    float4 v0 = p[0], v1 = p[1];
    __half2 h[4];
    h[0] = __float22half2_rn(make_float2(v0.x, v0.y));
    h[1] = __float22half2_rn(make_float2(v0.z, v0.w));
    h[2] = __float22half2_rn(make_float2(v1.x, v1.y));
    h[3] = __float22half2_rn(make_float2(v1.z, v1.w));
    *reinterpret_cast<uint4*>(g_Yh + (size_t)r * D_DIM + c8 * 8) =
        *reinterpret_cast<uint4*>(h);
    float s = v0.x * v0.x + v0.y * v0.y + v0.z * v0.z + v0.w * v0.w
            + v1.x * v1.x + v1.y * v1.y + v1.z * v1.z + v1.w * v1.w;
    s += __shfl_down_sync(0xffffffffu, s, 4, 8);
    s += __shfl_down_sync(0xffffffffu, s, 2, 8);
    s += __shfl_down_sync(0xffffffffu, s, 1, 8);
    if (c8 == 0) g_tysq[r] = s;
}

__global__ void prep_kernel(const float* __restrict__ psi) {
    __shared__ float red_t[1024];
    __shared__ float red_p[1024];
    __shared__ float inv_mv_s;
    int t = threadIdx.x;
    float st = 0.f, sp = 0.f;
    for (int m = t; m < M_TGT; m += 1024) { st += g_tysq[m]; sp += psi[m]; }
    red_t[t] = st; red_p[t] = sp;
    __syncthreads();
    for (int off = 512; off > 0; off >>= 1) {
        if (t < off) { red_t[t] += red_t[t + off]; red_p[t] += red_p[t + off]; }
        __syncthreads();
    }
    if (t == 0) {
        float mv = red_t[0] / (float)M_TGT;
        float inv_mv = 1.0f / mv;
        g_scalars[0] = inv_mv;
        g_scalars[1] = 2.0f * inv_mv * INV_REG * LOG2E;
        g_scalars[2] = red_p[0] / (float)M_TGT;
        inv_mv_s = inv_mv;
    }
    __syncthreads();
    float inv_mv = inv_mv_s;
    for (int m = t; m < M_TGT; m += 1024)
        g_c2[m] = (psi[m] - g_tysq[m] * inv_mv) * (INV_REG * LOG2E);
}

// ---------------- main kernel: 16 warps, warp-tile 32x32, persistent ----------
extern __shared__ char smem[];

__global__ __launch_bounds__(NT, 1)
void lse_mma_kernel() {
    const uint32_t sb = smem_u32(smem);
    const int tid  = threadIdx.x;
    const int lane = tid & 31;
    const int wid  = tid >> 5;
    const int mwarp = wid & 3;           // rows mwarp*32..+31
    const int nwarp = wid >> 2;          // cols nwarp*32..+31
    const int q  = lane & 3;
    const int g4 = lane >> 2;

    const float s2 = g_scalars[1];

    const uint64_t Yg = gmem_u64(g_Yh);
    const uint64_t Cg = gmem_u64(g_c2);

    const int b = lane >> 3, lr = lane & 7;
    const int rselA = (b & 1) * 8, cselA = b >> 1;
    const int rselB = (b >> 1) * 8, cselB = b & 1;

    for (int job = blockIdx.x; job < NJOBS; job += GRID) {
        const int rb = job >> 2;
        const int ck = job & 3;
        const int rowBase = rb * BM;
        const int tile0 = ck * TPC;

        __syncthreads();

        // ---- X tile (fp16) -> smem : 1024 chunks / 512 threads ----
#pragma unroll
        for (int i = 0; i < 2; i++) {
            int idx = tid + i * NT;
            int row = idx >> 3, ch = idx & 7;
            uint4 v = *reinterpret_cast<const uint4*>(
                reinterpret_cast<const char*>(g_Xh) +
                (uint64_t)(rowBase + row) * 128 + ch * 16);
            *reinterpret_cast<uint4*>(smem + SM_X + row * 128 +
                                      ((ch ^ (row & 7)) << 4)) = v;
        }
        // ---- prefetch Y tiles tile0..tile0+2 ----
#pragma unroll
        for (int pt = 0; pt < NSTAGE - 1; pt++) {
#pragma unroll
            for (int i = 0; i < 2; i++) {
                int idx = tid + i * NT;
                int row = idx >> 3, ch = idx & 7;
                uint32_t s = sb + SM_Y + pt * 16384 + row * 128 + ((ch ^ (row & 7)) << 4);
                uint64_t g = Yg + (uint64_t)((tile0 + pt) * BN + row) * 128 + ch * 16;
                CP_ASYNC16(s, g);
            }
            if (tid < 32) {
                uint32_t s = sb + SM_C + pt * 512 + tid * 16;
                uint64_t g = Cg + (uint64_t)((tile0 + pt) * BN + tid * 4) * 4;
                CP_ASYNC16(s, g);
            }
            CP_COMMIT();
        }
        __syncthreads();

        // ---- A fragments: M=32 (2 x m16), K=64 (4 x k16) = 32 regs ----
        uint32_t A[2][4][4];
#pragma unroll
        for (int mt = 0; mt < 2; mt++)
#pragma unroll
            for (int ks = 0; ks < 4; ks++) {
                int row = mwarp * 32 + mt * 16 + rselA + lr;
                int ch  = ks * 2 + cselA;
                ldsm4(A[mt][ks], sb + SM_X + row * 128 + ((ch ^ lr) << 4));
            }

        float runm[4], runs[4];   // [mt*2 + rowhalf]
#pragma unroll
        for (int r = 0; r < 4; r++) { runm[r] = -INFINITY; runs[r] = 0.f; }

        for (int t = 0; t < TPC; t++) {
            CP_WAIT(2);
            __syncthreads();
            const int buf = t & (NSTAGE - 1);
            const uint32_t yb = sb + SM_Y + buf * 16384;

            if (t + NSTAGE - 1 < TPC) {
                const int ft = t + NSTAGE - 1;
                const int fb = ft & (NSTAGE - 1);
#pragma unroll
                for (int i = 0; i < 2; i++) {
                    int idx = tid + i * NT;
                    int row = idx >> 3, ch = idx & 7;
                    uint32_t s = sb + SM_Y + fb * 16384 + row * 128 +
                                 ((ch ^ (row & 7)) << 4);
                    uint64_t g = Yg + (uint64_t)((tile0 + ft) * BN + row) * 128 + ch * 16;
                    CP_ASYNC16(s, g);
                }
                if (tid < 32) {
                    uint32_t s = sb + SM_C + fb * 512 + tid * 16;
                    uint64_t g = Cg + (uint64_t)((tile0 + ft) * BN + tid * 4) * 4;
                    CP_ASYNC16(s, g);
                }
            }
            CP_COMMIT();

            // c fragments for this warp's 32 cols: 4 x float2
            float2 cpv[4];
            {
                const float* cbB = reinterpret_cast<const float*>(smem + SM_C + buf * 512)
                                   + nwarp * 32;
#pragma unroll
                for (int nt = 0; nt < 4; nt++)
                    cpv[nt] = *reinterpret_cast<const float2*>(cbB + nt * 8 + q * 2);
            }

            // ---- two half-tiles of 16 cols: MMA then immediate epilogue ----
#pragma unroll
            for (int nt2 = 0; nt2 < 2; nt2++) {
                const uint32_t rowb =
                    yb + (uint32_t)(nwarp * 32 + nt2 * 16 + rselB + lr) * 128;
                float acc[2][2][4];
#pragma unroll
                for (int mt = 0; mt < 2; mt++)
#pragma unroll
                    for (int nt = 0; nt < 2; nt++)
#pragma unroll
                        for (int j = 0; j < 4; j++) acc[mt][nt][j] = 0.f;

#pragma unroll
                for (int ks = 0; ks < 4; ks++) {
                    uint32_t B[4];
                    ldsm4(B, rowb + (((ks * 2 + cselB) ^ lr) << 4));
#pragma unroll
                    for (int mt = 0; mt < 2; mt++) {
                        mma_f16(acc[mt][0], A[mt][ks], B[0], B[1]);
                        mma_f16(acc[mt][1], A[mt][ks], B[2], B[3]);
                    }
                }

                // epilogue: per (mt, rowhalf): 4 values
#pragma unroll
                for (int mt = 0; mt < 2; mt++) {
#pragma unroll
                    for (int hf = 0; hf < 2; hf++) {
                        const int r = mt * 2 + hf;
                        const int j0 = hf * 2;       // c0,c1 row g4; c2,c3 row g4+8
                        float v0 = fmaf(s2, acc[mt][0][j0 + 0], cpv[nt2 * 2 + 0].x);
                        float v1 = fmaf(s2, acc[mt][0][j0 + 1], cpv[nt2 * 2 + 0].y);
                        float v2 = fmaf(s2, acc[mt][1][j0 + 0], cpv[nt2 * 2 + 1].x);
                        float v3 = fmaf(s2, acc[mt][1][j0 + 1], cpv[nt2 * 2 + 1].y);
                        float mx = fmaxf(fmaxf(v0, v1), fmaxf(v2, v3));
                        if (mx > runm[r] - 20.f) {
                            if (mx > runm[r]) {
                                runs[r] *= ex2f(runm[r] - mx);
                                runm[r] = mx;
                            }
                            runs[r] += (ex2f(v0 - runm[r]) + ex2f(v1 - runm[r]))
                                     + (ex2f(v2 - runm[r]) + ex2f(v3 - runm[r]));
                        }
                    }
                }
            }
        }

        // ---- merge across 4 q-lanes per row; write partials ----
#pragma unroll
        for (int r = 0; r < 4; r++) {
            float m = runm[r], s = runs[r];
#pragma unroll
            for (int off = 1; off < 4; off <<= 1) {
                float m2 = __shfl_xor_sync(0xffffffffu, m, off);
                float s2x = __shfl_xor_sync(0xffffffffu, s, off);
                float nm = fmaxf(m, m2);
                s = s * ex2f(m - nm) + s2x * ex2f(m2 - nm);
                m = nm;
            }
            if (q == 0) {
                int mt = r >> 1, hf = r & 1;
                int rl = mwarp * 32 + mt * 16 + hf * 8 + g4;
                int idx = ((rb * NCHUNK + ck) * 4 + nwarp) * BM + rl;
                g_pm[idx] = m;
                g_ps[idx] = s;
            }
        }
    }
}

// ---------------- finalize: merge 16 partials/row ----------------
__global__ void final_kernel(const float* __restrict__ X, float* __restrict__ out) {
    int r = blockIdx.x * blockDim.x + threadIdx.x;
    if (r >= N_SRC) return;
    int rb = r >> 7, rl = r & 127;
    const float invmv = g_scalars[0];
    const float mpsi  = g_scalars[2];
    float m = -INFINITY, s = 0.f;
#pragma unroll
    for (int ck = 0; ck < NCHUNK; ck++)
#pragma unroll
        for (int nw = 0; nw < 4; nw++) {
            int idx = ((rb * NCHUNK + ck) * 4 + nw) * BM + rl;
            float m2 = g_pm[idx], s2v = g_ps[idx];
            float nm = fmaxf(m, m2);
            s = s * ex2f(m - nm) + s2v * ex2f(m2 - nm);
            m = nm;
        }
    const float4* xr = reinterpret_cast<const float4*>(X + (size_t)r * D_DIM);
    float xs = 0.f;
#pragma unroll
    for (int i = 0; i < 16; i++) {
        float4 v = xr[i];
        xs = fmaf(v.x, v.x, fmaf(v.y, v.y, fmaf(v.z, v.z, fmaf(v.w, v.w, xs))));
    }
    out[r] = fmaf(xs, invmv, mpsi) - (REG_P * LN2) * (m + lg2f(s));
}

// ---------------- launch ----------------
extern "C" void kernel_launch(void* const* d_in, const int* in_sizes, int n_in,
                              void* d_out, int out_size) {
    const float *X = nullptr, *Y = nullptr, *psi = nullptr;
    for (int i = 0; i < n_in; i++) {
        if (in_sizes[i] == N_SRC * D_DIM)      X   = (const float*)d_in[i];
        else if (in_sizes[i] == M_TGT * D_DIM) Y   = (const float*)d_in[i];
        else if (in_sizes[i] == M_TGT)         psi = (const float*)d_in[i];
    }
    float* out = (float*)d_out;

    convX_kernel<<<(N_SRC * D_DIM / 2 + 255) / 256, 256>>>(X);
    convY_tysq_kernel<<<(M_TGT * 8) / 256, 256>>>(Y);
    prep_kernel<<<1, 1024>>>(psi);

    cudaFuncSetAttribute(lse_mma_kernel,
                         cudaFuncAttributeMaxDynamicSharedMemorySize, SM_TOTAL);
    lse_mma_kernel<<<GRID, NT, SM_TOTAL>>>();

    final_kernel<<<N_SRC / 256, 256>>>(X, out);
}

// round 9
// speedup vs baseline: 5.2074x; 1.0873x over previous
#include <cuda_runtime.h>
#include <cuda_fp16.h>
#include <math.h>
#include <cstdint>

#define N_SRC 32768
#define M_TGT 8192
#define D_DIM 64
#define REG_P 0.01f
#define INV_REG 100.0f
#define LOG2E 1.4426950408889634f
#define LN2 0.6931471805599453f

#define BM 128
#define BN 128
#define NT 512
#define GRID 148
#define NRB (N_SRC / BM)        // 256 row-blocks
#define NCHUNK 4
#define TPC 16                  // tiles per chunk
#define NPAIR (TPC / 2)         // 8
#define NJOBS (NRB * NCHUNK)    // 1024
#define NSTAGE 6                // 3 pairs of Y stages

// ---------------- scratch ----------------
__device__ float  g_tysq[M_TGT];
__device__ float  g_c2[M_TGT];
__device__ float  g_scalars[4];      // 0: 1/mv, 1: 2*invmv*INV_REG*LOG2E, 2: mean(psi)
__device__ __half g_Xh[N_SRC * D_DIM];
__device__ __half g_Yh[M_TGT * D_DIM];
__device__ float  g_pm[NRB * NCHUNK * 4 * BM];   // [rb][ck][nwarp][row]
__device__ float  g_ps[NRB * NCHUNK * 4 * BM];

// ---------------- helpers ----------------
__device__ __forceinline__ uint32_t smem_u32(const void* p) {
    uint32_t a;
    asm("{ .reg .u64 t; cvta.to.shared.u64 t, %1; cvt.u32.u64 %0, t; }" : "=r"(a) : "l"(p));
    return a;
}
__device__ __forceinline__ uint64_t gmem_u64(const void* p) {
    uint64_t a;
    asm("cvta.to.global.u64 %0, %1;" : "=l"(a) : "l"(p));
    return a;
}
__device__ __forceinline__ float ex2f(float x) {
    float r; asm("ex2.approx.ftz.f32 %0, %1;" : "=f"(r) : "f"(x)); return r;
}
__device__ __forceinline__ float lg2f(float x) {
    float r; asm("lg2.approx.f32 %0, %1;" : "=f"(r) : "f"(x)); return r;
}

#define CP_ASYNC16(s, g) \
    asm volatile("cp.async.cg.shared.global [%0], [%1], 16;" :: "r"(s), "l"(g))
#define CP_COMMIT() asm volatile("cp.async.commit_group;" ::: "memory")
#define CP_WAIT(n)  asm volatile("cp.async.wait_group %0;" :: "n"(n) : "memory")

__device__ __forceinline__ void ldsm4(uint32_t* r, uint32_t addr) {
    asm volatile("ldmatrix.sync.aligned.m8n8.x4.shared.b16 {%0,%1,%2,%3}, [%4];"
                 : "=r"(r[0]), "=r"(r[1]), "=r"(r[2]), "=r"(r[3]) : "r"(addr));
}
__device__ __forceinline__ void mma_f16(float* c, const uint32_t* a,
                                        uint32_t b0, uint32_t b1) {
    asm volatile("mma.sync.aligned.m16n8k16.row.col.f32.f16.f16.f32 "
                 "{%0,%1,%2,%3}, {%4,%5,%6,%7}, {%8,%9}, {%0,%1,%2,%3};"
                 : "+f"(c[0]), "+f"(c[1]), "+f"(c[2]), "+f"(c[3])
                 : "r"(a[0]), "r"(a[1]), "r"(a[2]), "r"(a[3]), "r"(b0), "r"(b1));
}

// smem layout (bytes): Xh 16KB | Yh 6x16KB | cs 6x512B
#define SM_X 0
#define SM_Y 16384
#define SM_C (16384 + NSTAGE * 16384)
#define SM_TOTAL (SM_C + NSTAGE * 512)      // 117760

// stage index for tile t (chunk-local)
#define STG(t) ((((t) >> 1) % 3) * 2 + ((t) & 1))

// ---------------- prologue kernels ----------------
__global__ void convX_kernel(const float* __restrict__ src) {
    int i = blockIdx.x * blockDim.x + threadIdx.x;
    if (i >= N_SRC * D_DIM / 2) return;
    float2 v = reinterpret_cast<const float2*>(src)[i];
    reinterpret_cast<__half2*>(g_Xh)[i] = __float22half2_rn(v);
}

__global__ void convY_tysq_kernel(const float* __restrict__ Y) {
    int gid = blockIdx.x * blockDim.x + threadIdx.x;
    int r = gid >> 3, c8 = gid & 7;
    const float4* p = reinterpret_cast<const float4*>(Y + (size_t)r * D_DIM + c8 * 8);
    float4 v0 = p[0], v1 = p[1];
    __half2 h[4];
    h[0] = __float22half2_rn(make_float2(v0.x, v0.y));
    h[1] = __float22half2_rn(make_float2(v0.z, v0.w));
    h[2] = __float22half2_rn(make_float2(v1.x, v1.y));
    h[3] = __float22half2_rn(make_float2(v1.z, v1.w));
    *reinterpret_cast<uint4*>(g_Yh + (size_t)r * D_DIM + c8 * 8) =
        *reinterpret_cast<uint4*>(h);
    float s = v0.x * v0.x + v0.y * v0.y + v0.z * v0.z + v0.w * v0.w
            + v1.x * v1.x + v1.y * v1.y + v1.z * v1.z + v1.w * v1.w;
    s += __shfl_down_sync(0xffffffffu, s, 4, 8);
    s += __shfl_down_sync(0xffffffffu, s, 2, 8);
    s += __shfl_down_sync(0xffffffffu, s, 1, 8);
    if (c8 == 0) g_tysq[r] = s;
}

__global__ void prep_kernel(const float* __restrict__ psi) {
    __shared__ float red_t[1024];
    __shared__ float red_p[1024];
    __shared__ float inv_mv_s;
    int t = threadIdx.x;
    float st = 0.f, sp = 0.f;
    for (int m = t; m < M_TGT; m += 1024) { st += g_tysq[m]; sp += psi[m]; }
    red_t[t] = st; red_p[t] = sp;
    __syncthreads();
    for (int off = 512; off > 0; off >>= 1) {
        if (t < off) { red_t[t] += red_t[t + off]; red_p[t] += red_p[t + off]; }
        __syncthreads();
    }
    if (t == 0) {
        float mv = red_t[0] / (float)M_TGT;
        float inv_mv = 1.0f / mv;
        g_scalars[0] = inv_mv;
        g_scalars[1] = 2.0f * inv_mv * INV_REG * LOG2E;
        g_scalars[2] = red_p[0] / (float)M_TGT;
        inv_mv_s = inv_mv;
    }
    __syncthreads();
    float inv_mv = inv_mv_s;
    for (int m = t; m < M_TGT; m += 1024)
        g_c2[m] = (psi[m] - g_tysq[m] * inv_mv) * (INV_REG * LOG2E);
}

// ---------------- main kernel ----------------
extern __shared__ char smem[];

__device__ __forceinline__ void prefetch_pair(uint32_t sb, uint64_t Yg, uint64_t Cg,
                                              int tile0, int p, int tid) {
    // pair p: tiles 2p, 2p+1 -> stages STG(2p), STG(2p+1)
#pragma unroll
    for (int i = 0; i < 4; i++) {
        int idx = tid + i * NT;              // 0..2047
        int tt  = idx >> 10;
        int rem = idx & 1023;
        int row = rem >> 3, ch = rem & 7;
        int t = p * 2 + tt;
        uint32_t s = sb + SM_Y + STG(t) * 16384 + row * 128 + ((ch ^ (row & 7)) << 4);
        uint64_t g = Yg + (uint64_t)((tile0 + t) * BN + row) * 128 + ch * 16;
        CP_ASYNC16(s, g);
    }
    if (tid < 64) {
        int tt = tid >> 5, l = tid & 31;
        int t = p * 2 + tt;
        uint32_t s = sb + SM_C + STG(t) * 512 + l * 16;
        uint64_t g = Cg + (uint64_t)((tile0 + t) * BN + l * 4) * 4;
        CP_ASYNC16(s, g);
    }
}

__global__ __launch_bounds__(NT, 1)
void lse_mma_kernel() {
    const uint32_t sb = smem_u32(smem);
    const int tid  = threadIdx.x;
    const int lane = tid & 31;
    const int wid  = tid >> 5;
    const int mwarp = wid & 3;           // rows mwarp*32..+31
    const int nwarp = wid >> 2;          // cols nwarp*32..+31
    const int q  = lane & 3;
    const int g4 = lane >> 2;

    const float s2 = g_scalars[1];

    const uint64_t Yg = gmem_u64(g_Yh);
    const uint64_t Cg = gmem_u64(g_c2);

    const int b = lane >> 3, lr = lane & 7;
    const int rselA = (b & 1) * 8, cselA = b >> 1;
    const int rselB = (b >> 1) * 8, cselB = b & 1;

    for (int job = blockIdx.x; job < NJOBS; job += GRID) {
        const int rb = job >> 2;
        const int ck = job & 3;
        const int rowBase = rb * BM;
        const int tile0 = ck * TPC;

        __syncthreads();

        // ---- X tile (fp16) -> smem ----
#pragma unroll
        for (int i = 0; i < 2; i++) {
            int idx = tid + i * NT;
            int row = idx >> 3, ch = idx & 7;
            uint4 v = *reinterpret_cast<const uint4*>(
                reinterpret_cast<const char*>(g_Xh) +
                (uint64_t)(rowBase + row) * 128 + ch * 16);
            *reinterpret_cast<uint4*>(smem + SM_X + row * 128 +
                                      ((ch ^ (row & 7)) << 4)) = v;
        }
        // ---- prefetch pairs 0 and 1 (tiles 0..3), one group each ----
        prefetch_pair(sb, Yg, Cg, tile0, 0, tid);
        CP_COMMIT();
        prefetch_pair(sb, Yg, Cg, tile0, 1, tid);
        CP_COMMIT();
        __syncthreads();   // X visible

        // ---- A fragments: M=32 (2 x m16), K=64 (4 x k16) = 32 regs ----
        uint32_t A[2][4][4];
#pragma unroll
        for (int mt = 0; mt < 2; mt++)
#pragma unroll
            for (int ks = 0; ks < 4; ks++) {
                int row = mwarp * 32 + mt * 16 + rselA + lr;
                int ch  = ks * 2 + cselA;
                ldsm4(A[mt][ks], sb + SM_X + row * 128 + ((ch ^ lr) << 4));
            }

        float runm[4], runs[4];   // [mt*2 + rowhalf]
#pragma unroll
        for (int r = 0; r < 4; r++) { runm[r] = -INFINITY; runs[r] = 0.f; }

        for (int p = 0; p < NPAIR; p++) {
            CP_WAIT(1);            // pair p landed (pair p+1 may be in flight)
            __syncthreads();       // all warps done with pair p-1's stages
            if (p + 2 < NPAIR)
                prefetch_pair(sb, Yg, Cg, tile0, p + 2, tid);
            CP_COMMIT();           // (possibly empty group)

#pragma unroll
            for (int tt = 0; tt < 2; tt++) {
                const int t = p * 2 + tt;
                const int buf = STG(t);
                const uint32_t yb = sb + SM_Y + buf * 16384;

                float2 cpv[4];
                {
                    const float* cbB =
                        reinterpret_cast<const float*>(smem + SM_C + buf * 512)
                        + nwarp * 32;
#pragma unroll
                    for (int nt = 0; nt < 4; nt++)
                        cpv[nt] = *reinterpret_cast<const float2*>(cbB + nt * 8 + q * 2);
                }

#pragma unroll
                for (int nt2 = 0; nt2 < 2; nt2++) {
                    const uint32_t rowb =
                        yb + (uint32_t)(nwarp * 32 + nt2 * 16 + rselB + lr) * 128;
                    float acc[2][2][4];
#pragma unroll
                    for (int mt = 0; mt < 2; mt++)
#pragma unroll
                        for (int nf = 0; nf < 2; nf++)
#pragma unroll
                            for (int j = 0; j < 4; j++) acc[mt][nf][j] = 0.f;

#pragma unroll
                    for (int ks = 0; ks < 4; ks++) {
                        uint32_t B[4];
                        ldsm4(B, rowb + (((ks * 2 + cselB) ^ lr) << 4));
#pragma unroll
                        for (int mt = 0; mt < 2; mt++) {
                            mma_f16(acc[mt][0], A[mt][ks], B[0], B[1]);
                            mma_f16(acc[mt][1], A[mt][ks], B[2], B[3]);
                        }
                    }

                    // epilogue: one prune region per mt (covers both row-halves)
#pragma unroll
                    for (int mt = 0; mt < 2; mt++) {
                        const int r0 = mt * 2, r1 = mt * 2 + 1;
                        float v00 = fmaf(s2, acc[mt][0][0], cpv[nt2 * 2 + 0].x);
                        float v01 = fmaf(s2, acc[mt][0][1], cpv[nt2 * 2 + 0].y);
                        float v02 = fmaf(s2, acc[mt][1][0], cpv[nt2 * 2 + 1].x);
                        float v03 = fmaf(s2, acc[mt][1][1], cpv[nt2 * 2 + 1].y);
                        float v10 = fmaf(s2, acc[mt][0][2], cpv[nt2 * 2 + 0].x);
                        float v11 = fmaf(s2, acc[mt][0][3], cpv[nt2 * 2 + 0].y);
                        float v12 = fmaf(s2, acc[mt][1][2], cpv[nt2 * 2 + 1].x);
                        float v13 = fmaf(s2, acc[mt][1][3], cpv[nt2 * 2 + 1].y);
                        float mx0 = fmaxf(fmaxf(v00, v01), fmaxf(v02, v03));
                        float mx1 = fmaxf(fmaxf(v10, v11), fmaxf(v12, v13));
                        if (fmaxf(mx0, mx1) >
                            fminf(runm[r0], runm[r1]) - 20.f) {
                            float nm0 = fmaxf(runm[r0], mx0);
                            float nm1 = fmaxf(runm[r1], mx1);
                            runs[r0] = runs[r0] * ex2f(runm[r0] - nm0)
                                     + ((ex2f(v00 - nm0) + ex2f(v01 - nm0))
                                      + (ex2f(v02 - nm0) + ex2f(v03 - nm0)));
                            runs[r1] = runs[r1] * ex2f(runm[r1] - nm1)
                                     + ((ex2f(v10 - nm1) + ex2f(v11 - nm1))
                                      + (ex2f(v12 - nm1) + ex2f(v13 - nm1)));
                            runm[r0] = nm0;
                            runm[r1] = nm1;
                        }
                    }
                }
            }
        }

        // ---- merge across 4 q-lanes per row; write partials ----
#pragma unroll
        for (int r = 0; r < 4; r++) {
            float m = runm[r], s = runs[r];
#pragma unroll
            for (int off = 1; off < 4; off <<= 1) {
                float m2 = __shfl_xor_sync(0xffffffffu, m, off);
                float s2x = __shfl_xor_sync(0xffffffffu, s, off);
                float nm = fmaxf(m, m2);
                s = s * ex2f(m - nm) + s2x * ex2f(m2 - nm);
                m = nm;
            }
            if (q == 0) {
                int mt = r >> 1, hf = r & 1;
                int rl = mwarp * 32 + mt * 16 + hf * 8 + g4;
                int idx = ((rb * NCHUNK + ck) * 4 + nwarp) * BM + rl;
                g_pm[idx] = m;
                g_ps[idx] = s;
            }
        }
    }
}

// ---------------- finalize: merge 16 partials/row ----------------
__global__ void final_kernel(const float* __restrict__ X, float* __restrict__ out) {
    int r = blockIdx.x * blockDim.x + threadIdx.x;
    if (r >= N_SRC) return;
    int rb = r >> 7, rl = r & 127;
    const float invmv = g_scalars[0];
    const float mpsi  = g_scalars[2];
    float m = -INFINITY, s = 0.f;
#pragma unroll
    for (int ck = 0; ck < NCHUNK; ck++)
#pragma unroll
        for (int nw = 0; nw < 4; nw++) {
            int idx = ((rb * NCHUNK + ck) * 4 + nw) * BM + rl;
            float m2 = g_pm[idx], s2v = g_ps[idx];
            float nm = fmaxf(m, m2);
            s = s * ex2f(m - nm) + s2v * ex2f(m2 - nm);
            m = nm;
        }
    const float4* xr = reinterpret_cast<const float4*>(X + (size_t)r * D_DIM);
    float xs = 0.f;
#pragma unroll
    for (int i = 0; i < 16; i++) {
        float4 v = xr[i];
        xs = fmaf(v.x, v.x, fmaf(v.y, v.y, fmaf(v.z, v.z, fmaf(v.w, v.w, xs))));
    }
    out[r] = fmaf(xs, invmv, mpsi) - (REG_P * LN2) * (m + lg2f(s));
}

// ---------------- launch ----------------
extern "C" void kernel_launch(void* const* d_in, const int* in_sizes, int n_in,
                              void* d_out, int out_size) {
    const float *X = nullptr, *Y = nullptr, *psi = nullptr;
    for (int i = 0; i < n_in; i++) {
        if (in_sizes[i] == N_SRC * D_DIM)      X   = (const float*)d_in[i];
        else if (in_sizes[i] == M_TGT * D_DIM) Y   = (const float*)d_in[i];
        else if (in_sizes[i] == M_TGT)         psi = (const float*)d_in[i];
    }
    float* out = (float*)d_out;

    convX_kernel<<<(N_SRC * D_DIM / 2 + 255) / 256, 256>>>(X);
    convY_tysq_kernel<<<(M_TGT * 8) / 256, 256>>>(Y);
    prep_kernel<<<1, 1024>>>(psi);

    cudaFuncSetAttribute(lse_mma_kernel,
                         cudaFuncAttributeMaxDynamicSharedMemorySize, SM_TOTAL);
    lse_mma_kernel<<<GRID, NT, SM_TOTAL>>>();

    final_kernel<<<N_SRC / 256, 256>>>(X, out);
}